// round 6
// baseline (speedup 1.0000x reference)
#include <cuda_runtime.h>
#include <cstdint>

#define NN 100000
#define EE 1600000
#define ND 64
#define ED 8
#define HD 128
#define MSGIN 138
#define LDA 130          // padded leading dim for transposed A tiles (2-way conflicts only)

// Scratch: per-node message aggregation buffer (zeroed every launch)
__device__ float g_aggr[(size_t)NN * HD];

// ---------------- helpers ----------------

__device__ __forceinline__ float silu_f(float v) {
    return v / (1.0f + __expf(-v));
}

__device__ __forceinline__ unsigned long long pk2(float lo, float hi) {
    unsigned long long r;
    asm("mov.b64 %0, {%1, %2};" : "=l"(r) : "f"(lo), "f"(hi));
    return r;
}
__device__ __forceinline__ float2 up2(unsigned long long v) {
    float2 r;
    asm("mov.b64 {%0, %1}, %2;" : "=f"(r.x), "=f"(r.y) : "l"(v));
    return r;
}
// packed dual-FMA: d.lo += a.lo*b.lo ; d.hi += a.hi*b.hi   (Blackwell FFMA2)
__device__ __forceinline__ void f2fma(unsigned long long& d, unsigned long long a, unsigned long long b) {
    asm("fma.rn.f32x2 %0, %1, %2, %0;" : "+l"(d) : "l"(a), "l"(b));
}

// 128xK (A^T in SMEM, LDA=130) x Kx128 (B in SMEM, LD=128) -> 128x128 tile.
// Thread (ty,tx): rows ty*8..+7, col pairs {i*32+tx*2, +1} for i=0..3.
__device__ __forceinline__ void gemm128(const float* __restrict__ As_,
                                        const float* __restrict__ Bs_,
                                        const float* __restrict__ bias,
                                        int K, int ty, int tx,
                                        unsigned long long acc[8][4]) {
    const int c0 = tx * 2;
#pragma unroll
    for (int i = 0; i < 4; i++) {
        unsigned long long bi = pk2(bias[i * 32 + c0], bias[i * 32 + c0 + 1]);
#pragma unroll
        for (int j = 0; j < 8; j++) acc[j][i] = bi;
    }
    const float* ap = As_ + ty * 8;
    const float* bp = Bs_ + c0;
#pragma unroll 2
    for (int k = 0; k < K; k++) {
        float2 aA = *(const float2*)(ap + k * LDA + 0);
        float2 aB = *(const float2*)(ap + k * LDA + 2);
        float2 aC = *(const float2*)(ap + k * LDA + 4);
        float2 aD = *(const float2*)(ap + k * LDA + 6);
        unsigned long long a2[8];
        a2[0] = pk2(aA.x, aA.x); a2[1] = pk2(aA.y, aA.y);
        a2[2] = pk2(aB.x, aB.x); a2[3] = pk2(aB.y, aB.y);
        a2[4] = pk2(aC.x, aC.x); a2[5] = pk2(aC.y, aC.y);
        a2[6] = pk2(aD.x, aD.x); a2[7] = pk2(aD.y, aD.y);
        unsigned long long b0 = *(const unsigned long long*)(bp + k * 128 + 0);
        unsigned long long b1 = *(const unsigned long long*)(bp + k * 128 + 32);
        unsigned long long b2 = *(const unsigned long long*)(bp + k * 128 + 64);
        unsigned long long b3 = *(const unsigned long long*)(bp + k * 128 + 96);
#pragma unroll
        for (int j = 0; j < 8; j++) {
            f2fma(acc[j][0], a2[j], b0);
            f2fma(acc[j][1], a2[j], b1);
            f2fma(acc[j][2], a2[j], b2);
            f2fma(acc[j][3], a2[j], b3);
        }
    }
}

// silu each acc element in place
__device__ __forceinline__ void silu_acc(unsigned long long acc[8][4]) {
#pragma unroll
    for (int j = 0; j < 8; j++)
#pragma unroll
        for (int i = 0; i < 4; i++) {
            float2 t = up2(acc[j][i]);
            acc[j][i] = pk2(silu_f(t.x), silu_f(t.y));
        }
}

// write acc (optionally silu'd) transposed into As[c*LDA + r]
__device__ __forceinline__ void store_T(float* As_, unsigned long long acc[8][4],
                                        int ty, int tx, bool do_silu) {
#pragma unroll
    for (int j = 0; j < 8; j++) {
        int r = ty * 8 + j;
#pragma unroll
        for (int i = 0; i < 4; i++) {
            float2 t = up2(acc[j][i]);
            int c = i * 32 + tx * 2;
            As_[(c + 0) * LDA + r] = do_silu ? silu_f(t.x) : t.x;
            As_[(c + 1) * LDA + r] = do_silu ? silu_f(t.y) : t.y;
        }
    }
}

// silu(T) . wvec per row, half-warp reduce, then scatter 3 atomics per edge
__device__ __forceinline__ void dot_reduce_scatter(unsigned long long acc[8][4],
                                                   const float* __restrict__ wv,
                                                   float bscal,
                                                   const float* __restrict__ srel,
                                                   const float* __restrict__ ssq,
                                                   const int* __restrict__ srow,
                                                   float* __restrict__ outp,
                                                   int ty, int tx) {
    float s[8];
#pragma unroll
    for (int j = 0; j < 8; j++) {
        float acc_s = 0.f;
#pragma unroll
        for (int i = 0; i < 4; i++) {
            float2 t = up2(acc[j][i]);
            int c = i * 32 + tx * 2;
            acc_s += silu_f(t.x) * wv[c] + silu_f(t.y) * wv[c + 1];
        }
        s[j] = acc_s;
    }
#pragma unroll
    for (int o = 8; o > 0; o >>= 1) {
#pragma unroll
        for (int j = 0; j < 8; j++) s[j] += __shfl_xor_sync(0xffffffffu, s[j], o);
    }
    if (tx == 0) {
#pragma unroll
        for (int j = 0; j < 8; j++) {
            int r = ty * 8 + j;
            float w = (s[j] + bscal) / (ssq[r] + 1e-8f);
            int rw = srow[r];
            float* o = outp + (size_t)rw * 3;
            atomicAdd(o + 0, srel[r * 3 + 0] * w);
            atomicAdd(o + 1, srel[r * 3 + 1] * w);
            atomicAdd(o + 2, srel[r * 3 + 2] * w);
        }
    }
}

// ---------------- init kernel ----------------

__global__ void init_kernel(const float* __restrict__ x, const float* __restrict__ v,
                            float* __restrict__ out) {
    int idx = blockIdx.x * blockDim.x + threadIdx.x;
    int stride = gridDim.x * blockDim.x;
    for (int k = idx; k < NN * HD; k += stride) g_aggr[k] = 0.f;
    for (int k = idx; k < NN * 3; k += stride) {
        out[(size_t)NN * ND + k] = x[k];                 // x_new seed
        out[(size_t)NN * ND + (size_t)NN * 3 + k] = v[k]; // v_new seed
    }
}

// ---------------- edge kernel ----------------
// SMEM floats: As 138*130=17940, Bs 138*128=17664, srel 384, ssq 128, wc2 128, wv2 128, srow/scol 256 ints
#define EDGE_SMEM_FLOATS (17940 + 17664 + 384 + 128 + 128 + 128 + 256)
#define EDGE_SMEM_BYTES  (EDGE_SMEM_FLOATS * 4)

__global__ void __launch_bounds__(256, 1)
edge_kernel(const float* __restrict__ h, const float* __restrict__ x,
            const int* __restrict__ ei, const float* __restrict__ ea,
            const float* __restrict__ Wm1, const float* __restrict__ bm1,
            const float* __restrict__ Wm2, const float* __restrict__ bm2,
            const float* __restrict__ Wc1, const float* __restrict__ bc1,
            const float* __restrict__ Wc2, const float* __restrict__ bc2,
            const float* __restrict__ Wv1, const float* __restrict__ bv1,
            const float* __restrict__ Wv2, const float* __restrict__ bv2,
            float* __restrict__ outx, float* __restrict__ outv) {
    extern __shared__ float sm[];
    float* As   = sm;                   // 17940
    float* Bs   = As + 17940;           // 17664
    float* srel = Bs + 17664;           // 384
    float* ssq  = srel + 384;           // 128
    float* swc2 = ssq + 128;            // 128
    float* swv2 = swc2 + 128;           // 128
    int*   srow = (int*)(swv2 + 128);   // 128
    int*   scol = srow + 128;           // 128

    const int tid = threadIdx.x;
    const int tx = tid & 15;
    const int ty = tid >> 4;
    const int e0 = blockIdx.x * 128;

    // ---- phase 0: edge metadata (edge_index is int32: JAX default x64-disabled) ----
    if (tid < 128) {
        int e = e0 + tid;
        int r = ei[e];
        int c = ei[EE + e];
        srow[tid] = r; scol[tid] = c;
        float dx = x[r * 3 + 0] - x[c * 3 + 0];
        float dy = x[r * 3 + 1] - x[c * 3 + 1];
        float dz = x[r * 3 + 2] - x[c * 3 + 2];
        srel[tid * 3 + 0] = dx; srel[tid * 3 + 1] = dy; srel[tid * 3 + 2] = dz;
        float sq = dx * dx + dy * dy + dz * dz;
        ssq[tid] = sq;
        As[128 * LDA + tid] = sq;   // feature 128: squared_dist
        As[129 * LDA + tid] = dz;   // feature 129: z_diff
        swc2[tid] = Wc2[tid];
        swv2[tid] = Wv2[tid];
    }
    __syncthreads();

    // ---- phase 1: gather msg_in^T into As ----
    {
        int el = tid >> 1, part = tid & 1;
        const float4* hr = (const float4*)h + (size_t)srow[el] * 16 + part * 8;
        const float4* hc = (const float4*)h + (size_t)scol[el] * 16 + part * 8;
#pragma unroll
        for (int q = 0; q < 8; q++) {
            float4 f = hr[q];
            int k0 = part * 32 + q * 4;
            As[(k0 + 0) * LDA + el] = f.x; As[(k0 + 1) * LDA + el] = f.y;
            As[(k0 + 2) * LDA + el] = f.z; As[(k0 + 3) * LDA + el] = f.w;
        }
#pragma unroll
        for (int q = 0; q < 8; q++) {
            float4 f = hc[q];
            int k0 = 64 + part * 32 + q * 4;
            As[(k0 + 0) * LDA + el] = f.x; As[(k0 + 1) * LDA + el] = f.y;
            As[(k0 + 2) * LDA + el] = f.z; As[(k0 + 3) * LDA + el] = f.w;
        }
#pragma unroll
        for (int it = 0; it < 4; it++) {
            int idx = tid + it * 256;          // 1024 = 128 edges * 8 attrs
            int e = idx >> 3, j = idx & 7;
            As[(130 + j) * LDA + e] = ea[(size_t)e0 * 8 + idx];
        }
    }
    // Bs <- Wm1
    for (int i4 = tid; i4 < (MSGIN * 128) / 4; i4 += 256)
        ((float4*)Bs)[i4] = ((const float4*)Wm1)[i4];
    __syncthreads();

    unsigned long long acc[8][4];

    // ---- GEMM1: msg_in @ Wm1 + bm1 ----
    gemm128(As, Bs, bm1, MSGIN, ty, tx, acc);
    __syncthreads();
    store_T(As, acc, ty, tx, true);   // silu, transposed
    for (int i4 = tid; i4 < (128 * 128) / 4; i4 += 256)
        ((float4*)Bs)[i4] = ((const float4*)Wm2)[i4];
    __syncthreads();

    // ---- GEMM2: -> msg ----
    gemm128(As, Bs, bm2, 128, ty, tx, acc);
    silu_acc(acc);                    // acc = msg

    // msg aggregation: coalesced atomics (half-warp spans 128B)
#pragma unroll
    for (int j = 0; j < 8; j++) {
        int r = ty * 8 + j;
        float* dst = g_aggr + (size_t)srow[r] * HD + tx * 2;
#pragma unroll
        for (int i = 0; i < 4; i++) {
            float2 m = up2(acc[j][i]);
            atomicAdd(dst + i * 32 + 0, m.x);
            atomicAdd(dst + i * 32 + 1, m.y);
        }
    }
    __syncthreads();
    store_T(As, acc, ty, tx, false);  // msg^T (already silu'd)
    for (int i4 = tid; i4 < (128 * 128) / 4; i4 += 256)
        ((float4*)Bs)[i4] = ((const float4*)Wc1)[i4];
    __syncthreads();

    // ---- GEMM3: coordinate weights ----
    gemm128(As, Bs, bc1, 128, ty, tx, acc);
    dot_reduce_scatter(acc, swc2, bc2[0], srel, ssq, srow, outx, ty, tx);
    __syncthreads();
    for (int i4 = tid; i4 < (128 * 128) / 4; i4 += 256)
        ((float4*)Bs)[i4] = ((const float4*)Wv1)[i4];
    __syncthreads();

    // ---- GEMM4: velocity weights ----
    gemm128(As, Bs, bv1, 128, ty, tx, acc);
    dot_reduce_scatter(acc, swv2, bv2[0], srel, ssq, srow, outv, ty, tx);
}

// ---------------- node kernel ----------------
// SMEM: As 192*130 = 24960, Bs 192*128 = 24576
#define NODE_SMEM_FLOATS (24960 + 24576)
#define NODE_SMEM_BYTES  (NODE_SMEM_FLOATS * 4)

__global__ void __launch_bounds__(256, 1)
node_kernel(const float* __restrict__ h,
            const float* __restrict__ Wn1, const float* __restrict__ bn1,
            const float* __restrict__ Wn2, const float* __restrict__ bn2,
            float* __restrict__ out) {
    extern __shared__ float sm[];
    float* As = sm;            // 24960
    float* Bs = As + 24960;    // 24576

    const int tid = threadIdx.x;
    const int tx = tid & 15;
    const int ty = tid >> 4;
    const int n0 = blockIdx.x * 128;

    // gather node_in^T = [h | aggr]^T
    {
        int r = tid >> 1, part = tid & 1;
        int n = n0 + r;
        int nc = (n < NN) ? n : (NN - 1);
        const float4* hr = (const float4*)h + (size_t)nc * 16 + part * 8;
#pragma unroll
        for (int q = 0; q < 8; q++) {
            float4 f = hr[q];
            int k0 = part * 32 + q * 4;
            As[(k0 + 0) * LDA + r] = f.x; As[(k0 + 1) * LDA + r] = f.y;
            As[(k0 + 2) * LDA + r] = f.z; As[(k0 + 3) * LDA + r] = f.w;
        }
        const float4* ar = (const float4*)g_aggr + (size_t)nc * 32 + part * 16;
#pragma unroll
        for (int q = 0; q < 16; q++) {
            float4 f = ar[q];
            int k0 = 64 + part * 64 + q * 4;
            As[(k0 + 0) * LDA + r] = f.x; As[(k0 + 1) * LDA + r] = f.y;
            As[(k0 + 2) * LDA + r] = f.z; As[(k0 + 3) * LDA + r] = f.w;
        }
    }
    for (int i4 = tid; i4 < (192 * 128) / 4; i4 += 256)
        ((float4*)Bs)[i4] = ((const float4*)Wn1)[i4];
    __syncthreads();

    unsigned long long acc[8][4];
    gemm128(As, Bs, bn1, 192, ty, tx, acc);
    __syncthreads();
    store_T(As, acc, ty, tx, true);   // silu, transposed
    for (int i4 = tid; i4 < (128 * 64) / 4; i4 += 256)
        ((float4*)Bs)[i4] = ((const float4*)Wn2)[i4];
    __syncthreads();

    // GEMM2: 128xK(128) * 128x64, LDB = 64
    unsigned long long a2b[8][2];
    {
        const int c0 = tx * 2;
#pragma unroll
        for (int i = 0; i < 2; i++) {
            unsigned long long bi = pk2(bn2[i * 32 + c0], bn2[i * 32 + c0 + 1]);
#pragma unroll
            for (int j = 0; j < 8; j++) a2b[j][i] = bi;
        }
        const float* ap = As + ty * 8;
        const float* bp = Bs + c0;
#pragma unroll 2
        for (int k = 0; k < 128; k++) {
            float2 aA = *(const float2*)(ap + k * LDA + 0);
            float2 aB = *(const float2*)(ap + k * LDA + 2);
            float2 aC = *(const float2*)(ap + k * LDA + 4);
            float2 aD = *(const float2*)(ap + k * LDA + 6);
            unsigned long long a2[8];
            a2[0] = pk2(aA.x, aA.x); a2[1] = pk2(aA.y, aA.y);
            a2[2] = pk2(aB.x, aB.x); a2[3] = pk2(aB.y, aB.y);
            a2[4] = pk2(aC.x, aC.x); a2[5] = pk2(aC.y, aC.y);
            a2[6] = pk2(aD.x, aD.x); a2[7] = pk2(aD.y, aD.y);
            unsigned long long b0 = *(const unsigned long long*)(bp + k * 64 + 0);
            unsigned long long b1 = *(const unsigned long long*)(bp + k * 64 + 32);
#pragma unroll
            for (int j = 0; j < 8; j++) {
                f2fma(a2b[j][0], a2[j], b0);
                f2fma(a2b[j][1], a2[j], b1);
            }
        }
    }
    // residual + store h_new
#pragma unroll
    for (int j = 0; j < 8; j++) {
        int n = n0 + ty * 8 + j;
        if (n < NN) {
#pragma unroll
            for (int i = 0; i < 2; i++) {
                int c = i * 32 + tx * 2;
                float2 hv = *(const float2*)(h + (size_t)n * 64 + c);
                float2 t = up2(a2b[j][i]);
                float2 o; o.x = hv.x + t.x; o.y = hv.y + t.y;
                *(float2*)(out + (size_t)n * 64 + c) = o;
            }
        }
    }
}

// ---------------- launch ----------------

extern "C" void kernel_launch(void* const* d_in, const int* in_sizes, int n_in,
                              void* d_out, int out_size) {
    const float* h   = (const float*)d_in[0];
    const float* x   = (const float*)d_in[1];
    const float* v   = (const float*)d_in[2];
    const int*   ei  = (const int*)d_in[3];      // int32 (JAX x64-disabled demotes int64)
    const float* ea  = (const float*)d_in[4];
    const float* Wm1 = (const float*)d_in[5];
    const float* bm1 = (const float*)d_in[6];
    const float* Wm2 = (const float*)d_in[7];
    const float* bm2 = (const float*)d_in[8];
    const float* Wn1 = (const float*)d_in[9];
    const float* bn1 = (const float*)d_in[10];
    const float* Wn2 = (const float*)d_in[11];
    const float* bn2 = (const float*)d_in[12];
    const float* Wc1 = (const float*)d_in[13];
    const float* bc1 = (const float*)d_in[14];
    const float* Wc2 = (const float*)d_in[15];
    const float* bc2 = (const float*)d_in[16];
    const float* Wv1 = (const float*)d_in[17];
    const float* bv1 = (const float*)d_in[18];
    const float* Wv2 = (const float*)d_in[19];
    const float* bv2 = (const float*)d_in[20];
    float* out = (float*)d_out;

    cudaFuncSetAttribute(edge_kernel, cudaFuncAttributeMaxDynamicSharedMemorySize, EDGE_SMEM_BYTES);
    cudaFuncSetAttribute(node_kernel, cudaFuncAttributeMaxDynamicSharedMemorySize, NODE_SMEM_BYTES);

    init_kernel<<<2048, 256>>>(x, v, out);
    edge_kernel<<<EE / 128, 256, EDGE_SMEM_BYTES>>>(
        h, x, ei, ea, Wm1, bm1, Wm2, bm2, Wc1, bc1, Wc2, bc2, Wv1, bv1, Wv2, bv2,
        out + (size_t)NN * ND, out + (size_t)NN * ND + (size_t)NN * 3);
    node_kernel<<<(NN + 127) / 128, 256, NODE_SMEM_BYTES>>>(h, Wn1, bn1, Wn2, bn2, out);
}

// round 8
// speedup vs baseline: 1.6466x; 1.6466x over previous
#include <cuda_runtime.h>
#include <cstdint>

#define NN 100000
#define EE 1600000
#define LKA 148   // As row stride (floats): conflict-free A fragments
#define LKB 136   // Bs row stride (floats): conflict-free B fragments
#define LDA 130   // node-kernel transposed stride (proven)

// ---------------- global scratch ----------------
__device__ float g_aggr[(size_t)NN * 128];

// ---------------- helpers ----------------
__device__ __forceinline__ float silu_f(float v) {
    return v / (1.0f + __expf(-v));
}
__device__ __forceinline__ uint32_t rna_tf32(float f) {
    uint32_t u; asm("cvt.rna.tf32.f32 %0, %1;" : "=r"(u) : "f"(f)); return u;
}
__device__ __forceinline__ unsigned long long pk2(float lo, float hi) {
    unsigned long long r; asm("mov.b64 %0, {%1, %2};" : "=l"(r) : "f"(lo), "f"(hi)); return r;
}
__device__ __forceinline__ float2 up2(unsigned long long v) {
    float2 r; asm("mov.b64 {%0, %1}, %2;" : "=f"(r.x), "=f"(r.y) : "l"(v)); return r;
}
__device__ __forceinline__ void f2fma(unsigned long long& d, unsigned long long a, unsigned long long b) {
    asm("fma.rn.f32x2 %0, %1, %2, %0;" : "+l"(d) : "l"(a), "l"(b));
}
// tf32 tensor-core mma (sm_80 baseline PTX -> works at target sm_103)
__device__ __forceinline__ void mma8(float c[4], const uint32_t a[4], uint32_t b0, uint32_t b1) {
    asm volatile("mma.sync.aligned.m16n8k8.row.col.f32.tf32.tf32.f32 "
                 "{%0,%1,%2,%3}, {%4,%5,%6,%7}, {%8,%9}, {%0,%1,%2,%3};"
                 : "+f"(c[0]), "+f"(c[1]), "+f"(c[2]), "+f"(c[3])
                 : "r"(a[0]), "r"(a[1]), "r"(a[2]), "r"(a[3]), "r"(b0), "r"(b1));
}

// ---------------- init ----------------
__global__ void init_kernel(const float* __restrict__ x, const float* __restrict__ v,
                            float* __restrict__ out) {
    int idx = blockIdx.x * blockDim.x + threadIdx.x;
    int stride = gridDim.x * blockDim.x;
    for (int k = idx; k < NN * 128; k += stride) g_aggr[k] = 0.f;
    for (int k = idx; k < NN * 3; k += stride) {
        out[(size_t)NN * 64 + k] = x[k];
        out[(size_t)NN * 64 + (size_t)NN * 3 + k] = v[k];
    }
}

// ---------------- edge kernel pieces ----------------

// copy weight [realRows][128] row-major -> Bs (tf32 bits), pad rows zeroed
__device__ __forceinline__ void load_B(uint32_t* __restrict__ Bs32, const float* __restrict__ W,
                                       int rows, int realRows, int tid) {
    for (int idx = tid; idx < rows * 32; idx += 256) {
        int k = idx >> 5, j = idx & 31;
        float4 w = make_float4(0.f, 0.f, 0.f, 0.f);
        if (k < realRows) w = ((const float4*)W)[k * 32 + j];
        uint4 u;
        u.x = rna_tf32(w.x); u.y = rna_tf32(w.y); u.z = rna_tf32(w.z); u.w = rna_tf32(w.w);
        *(uint4*)(Bs32 + k * LKB + j * 4) = u;
    }
}

// warp GEMM: rows [rw0, rw0+32), cols [cn0, cn0+64), C = A @ B + bias (bias pre-folded into c init)
__device__ __forceinline__ void warp_gemm(const uint32_t* __restrict__ As32,
                                          const uint32_t* __restrict__ Bs32,
                                          const float* __restrict__ bias,
                                          int KB, bool cvtA,
                                          int rw0, int cn0, int g, int t,
                                          float c[2][8][4]) {
#pragma unroll
    for (int nt = 0; nt < 8; nt++) {
        float b0v = bias[cn0 + nt * 8 + 2 * t];
        float b1v = bias[cn0 + nt * 8 + 2 * t + 1];
        c[0][nt][0] = b0v; c[0][nt][1] = b1v; c[0][nt][2] = b0v; c[0][nt][3] = b1v;
        c[1][nt][0] = b0v; c[1][nt][1] = b1v; c[1][nt][2] = b0v; c[1][nt][3] = b1v;
    }
#pragma unroll 1
    for (int kb = 0; kb < KB; kb++) {
        uint32_t a[2][4];
#pragma unroll
        for (int mh = 0; mh < 2; mh++) {
            const uint32_t* p0 = As32 + (rw0 + mh * 16 + g) * LKA + kb * 8 + t;
            const uint32_t* p1 = p0 + 8 * LKA;
            a[mh][0] = p0[0]; a[mh][1] = p1[0]; a[mh][2] = p0[4]; a[mh][3] = p1[4];
            if (cvtA) {
#pragma unroll
                for (int j = 0; j < 4; j++) a[mh][j] = rna_tf32(__uint_as_float(a[mh][j]));
            }
        }
#pragma unroll
        for (int nt = 0; nt < 8; nt++) {
            uint32_t b0 = Bs32[(kb * 8 + t) * LKB + cn0 + nt * 8 + g];
            uint32_t b1 = Bs32[(kb * 8 + t + 4) * LKB + cn0 + nt * 8 + g];
            mma8(c[0][nt], a[0], b0, b1);
            mma8(c[1][nt], a[1], b0, b1);
        }
    }
}

// write silu(c) into As rows (own stripe), tf32 bits or f32
__device__ __forceinline__ void store_act(float* __restrict__ As, float c[2][8][4],
                                          int rw0, int cn0, int g, int t, bool cvt) {
#pragma unroll
    for (int mh = 0; mh < 2; mh++) {
        int r0 = rw0 + mh * 16 + g;
#pragma unroll
        for (int nt = 0; nt < 8; nt++) {
            int col = cn0 + nt * 8 + 2 * t;
            float v0 = silu_f(c[mh][nt][0]);
            float v1 = silu_f(c[mh][nt][1]);
            float v2 = silu_f(c[mh][nt][2]);
            float v3 = silu_f(c[mh][nt][3]);
            if (cvt) {
                v0 = __uint_as_float(rna_tf32(v0)); v1 = __uint_as_float(rna_tf32(v1));
                v2 = __uint_as_float(rna_tf32(v2)); v3 = __uint_as_float(rna_tf32(v3));
            }
            *(float2*)(As + r0 * LKA + col) = make_float2(v0, v1);
            *(float2*)(As + (r0 + 8) * LKA + col) = make_float2(v2, v3);
        }
    }
}

// row-dot with w2 after silu, quad-reduce, stage per-row sums into sred[row]
__device__ __forceinline__ void reduce_rows(float c[2][8][4], const float* __restrict__ w2,
                                            float* __restrict__ sredh,
                                            int rw0, int cn0, int g, int t) {
#pragma unroll
    for (int mh = 0; mh < 2; mh++) {
        float s0 = 0.f, s1 = 0.f;
#pragma unroll
        for (int nt = 0; nt < 8; nt++) {
            int col = cn0 + nt * 8 + 2 * t;
            float w0 = w2[col], w1 = w2[col + 1];
            s0 += silu_f(c[mh][nt][0]) * w0 + silu_f(c[mh][nt][1]) * w1;
            s1 += silu_f(c[mh][nt][2]) * w0 + silu_f(c[mh][nt][3]) * w1;
        }
        s0 += __shfl_xor_sync(0xffffffffu, s0, 1);
        s0 += __shfl_xor_sync(0xffffffffu, s0, 2);
        s1 += __shfl_xor_sync(0xffffffffu, s1, 1);
        s1 += __shfl_xor_sync(0xffffffffu, s1, 2);
        if (t == 0) {
            sredh[rw0 + mh * 16 + g] = s0;
            sredh[rw0 + mh * 16 + g + 8] = s1;
        }
    }
}

// SMEM floats: As 18944, Bs 19584, sbias 768, ssq 128, srel 384, sredp 128, sredq 128, srow/scol 256 int
#define EDGE_SMEM_FLOATS (18944 + 19584 + 768 + 128 + 384 + 128 + 128 + 256)
#define EDGE_SMEM_BYTES  (EDGE_SMEM_FLOATS * 4)

__global__ void __launch_bounds__(256, 1)
edge_mma_kernel(const float* __restrict__ h, const float* __restrict__ x,
                const int* __restrict__ ei, const float* __restrict__ ea,
                const float* __restrict__ Wm1, const float* __restrict__ bm1,
                const float* __restrict__ Wm2, const float* __restrict__ bm2,
                const float* __restrict__ Wc1, const float* __restrict__ bc1,
                const float* __restrict__ Wc2, const float* __restrict__ bc2,
                const float* __restrict__ Wv1, const float* __restrict__ bv1,
                const float* __restrict__ Wv2, const float* __restrict__ bv2,
                float* __restrict__ outx, float* __restrict__ outv) {
    extern __shared__ float sm[];
    float* As    = sm;                    // 18944 = 128*148
    float* Bs    = As + 18944;            // 19584 = 144*136
    float* sbias = Bs + 19584;            // 768: bm1|bm2|bc1|bv1|Wc2|Wv2
    float* ssq   = sbias + 768;           // 128
    float* srel  = ssq + 128;             // 384
    float* sredp = srel + 384;            // 128
    float* sredq = sredp + 128;           // 128
    int*   srow  = (int*)(sredq + 128);   // 128
    int*   scol  = srow + 128;            // 128
    uint32_t* As32 = (uint32_t*)As;
    uint32_t* Bs32 = (uint32_t*)Bs;

    const int tid = threadIdx.x;
    const int w = tid >> 5, lane = tid & 31;
    const int g = lane >> 2, t = lane & 3;
    const int rw0 = (w & 3) * 32, cn0 = (w >> 2) * 64;
    const int e0 = blockIdx.x * 128;

    // ---- phase 0: metadata (tid<128) + bias staging (tid>=128) ----
    if (tid < 128) {
        int e = e0 + tid;
        int r = ei[e], cc = ei[EE + e];
        srow[tid] = r; scol[tid] = cc;
        float dx = x[r * 3 + 0] - x[cc * 3 + 0];
        float dy = x[r * 3 + 1] - x[cc * 3 + 1];
        float dz = x[r * 3 + 2] - x[cc * 3 + 2];
        float sq = dx * dx + dy * dy + dz * dz;
        ssq[tid] = sq;
        srel[tid * 3 + 0] = dx; srel[tid * 3 + 1] = dy; srel[tid * 3 + 2] = dz;
        float4 ea0 = ((const float4*)(ea + (size_t)e * 8))[0];
        float4 ea1 = ((const float4*)(ea + (size_t)e * 8))[1];
        uint32_t* dst = As32 + tid * LKA + 128;
        uint4 u;
        u.x = rna_tf32(sq);    u.y = rna_tf32(dz);    u.z = rna_tf32(ea0.x); u.w = rna_tf32(ea0.y);
        *(uint4*)(dst + 0) = u;
        u.x = rna_tf32(ea0.z); u.y = rna_tf32(ea0.w); u.z = rna_tf32(ea1.x); u.w = rna_tf32(ea1.y);
        *(uint4*)(dst + 4) = u;
        u.x = rna_tf32(ea1.z); u.y = rna_tf32(ea1.w); u.z = 0u; u.w = 0u;
        *(uint4*)(dst + 8) = u;
        *(uint4*)(dst + 12) = make_uint4(0u, 0u, 0u, 0u);
    } else {
        for (int i = tid - 128; i < 768; i += 128) {
            int j = i & 127, gg = i >> 7;
            sbias[i] = (gg == 0) ? bm1[j] : (gg == 1) ? bm2[j] : (gg == 2) ? bc1[j] :
                       (gg == 3) ? bv1[j] : (gg == 4) ? Wc2[j] : Wv2[j];
        }
    }
    __syncthreads();

    // ---- gather h rows (tf32) + load Wm1 ----
    {
        int r = tid >> 1, part = tid & 1;
        int node = part ? scol[r] : srow[r];
        const float4* hp = (const float4*)(h + (size_t)node * 64);
        uint32_t* dst = As32 + r * LKA + part * 64;
#pragma unroll
        for (int q = 0; q < 16; q++) {
            float4 f = hp[q];
            uint4 u;
            u.x = rna_tf32(f.x); u.y = rna_tf32(f.y); u.z = rna_tf32(f.z); u.w = rna_tf32(f.w);
            *(uint4*)(dst + q * 4) = u;
        }
    }
    load_B(Bs32, Wm1, 144, 138, tid);
    __syncthreads();

    float c[2][8][4];

    // ---- GEMM1: msg_in @ Wm1 + bm1 -> H1 = silu (tf32 into As) ----
    warp_gemm(As32, Bs32, sbias + 0, 18, false, rw0, cn0, g, t, c);
    store_act(As, c, rw0, cn0, g, t, true);
    __syncthreads();
    load_B(Bs32, Wm2, 128, 128, tid);
    __syncthreads();

    // ---- GEMM2: H1 @ Wm2 + bm2 -> msg = silu (f32 into As) ----
    warp_gemm(As32, Bs32, sbias + 128, 16, false, rw0, cn0, g, t, c);
    store_act(As, c, rw0, cn0, g, t, false);
    __syncthreads();

    // ---- aggregation (coalesced vector reds) + load Wc1 ----
    {
        int r = tid >> 1, part = tid & 1;
        const float* src = As + r * LKA + part * 64;
        float* dst = g_aggr + (size_t)srow[r] * 128 + part * 64;
#pragma unroll
        for (int q = 0; q < 16; q++) {
            float4 vv = *(const float4*)(src + q * 4);
            asm volatile("red.global.add.v4.f32 [%0], {%1,%2,%3,%4};"
                :: "l"(dst + q * 4), "f"(vv.x), "f"(vv.y), "f"(vv.z), "f"(vv.w) : "memory");
        }
    }
    load_B(Bs32, Wc1, 128, 128, tid);
    __syncthreads();

    // ---- GEMM3: msg @ Wc1 + bc1 -> x-weights ----
    warp_gemm(As32, Bs32, sbias + 256, 16, true, rw0, cn0, g, t, c);
    reduce_rows(c, sbias + 512, (w >> 2) ? sredq : sredp, rw0, cn0, g, t);
    __syncthreads();
    if (tid < 128) {
        float tot = sredp[tid] + sredq[tid] + bc2[0];
        float wv = __fdividef(tot, ssq[tid] + 1e-8f);
        int rw = srow[tid];
        atomicAdd(outx + (size_t)rw * 3 + 0, srel[tid * 3 + 0] * wv);
        atomicAdd(outx + (size_t)rw * 3 + 1, srel[tid * 3 + 1] * wv);
        atomicAdd(outx + (size_t)rw * 3 + 2, srel[tid * 3 + 2] * wv);
    }
    load_B(Bs32, Wv1, 128, 128, tid);
    __syncthreads();

    // ---- GEMM4: msg @ Wv1 + bv1 -> v-weights ----
    warp_gemm(As32, Bs32, sbias + 384, 16, true, rw0, cn0, g, t, c);
    reduce_rows(c, sbias + 640, (w >> 2) ? sredq : sredp, rw0, cn0, g, t);
    __syncthreads();
    if (tid < 128) {
        float tot = sredp[tid] + sredq[tid] + bv2[0];
        float wv = __fdividef(tot, ssq[tid] + 1e-8f);
        int rw = srow[tid];
        atomicAdd(outv + (size_t)rw * 3 + 0, srel[tid * 3 + 0] * wv);
        atomicAdd(outv + (size_t)rw * 3 + 1, srel[tid * 3 + 1] * wv);
        atomicAdd(outv + (size_t)rw * 3 + 2, srel[tid * 3 + 2] * wv);
    }
}

// ---------------- node kernel (FFMA2, proven from round 4) ----------------
__device__ __forceinline__ void gemm128n(const float* __restrict__ As_,
                                         const float* __restrict__ Bs_,
                                         const float* __restrict__ bias,
                                         int K, int ty, int tx,
                                         unsigned long long acc[8][4]) {
    const int c0 = tx * 2;
#pragma unroll
    for (int i = 0; i < 4; i++) {
        unsigned long long bi = pk2(bias[i * 32 + c0], bias[i * 32 + c0 + 1]);
#pragma unroll
        for (int j = 0; j < 8; j++) acc[j][i] = bi;
    }
    const float* ap = As_ + ty * 8;
    const float* bp = Bs_ + c0;
#pragma unroll 2
    for (int k = 0; k < K; k++) {
        float2 aA = *(const float2*)(ap + k * LDA + 0);
        float2 aB = *(const float2*)(ap + k * LDA + 2);
        float2 aC = *(const float2*)(ap + k * LDA + 4);
        float2 aD = *(const float2*)(ap + k * LDA + 6);
        unsigned long long a2[8];
        a2[0] = pk2(aA.x, aA.x); a2[1] = pk2(aA.y, aA.y);
        a2[2] = pk2(aB.x, aB.x); a2[3] = pk2(aB.y, aB.y);
        a2[4] = pk2(aC.x, aC.x); a2[5] = pk2(aC.y, aC.y);
        a2[6] = pk2(aD.x, aD.x); a2[7] = pk2(aD.y, aD.y);
        unsigned long long b0 = *(const unsigned long long*)(bp + k * 128 + 0);
        unsigned long long b1 = *(const unsigned long long*)(bp + k * 128 + 32);
        unsigned long long b2 = *(const unsigned long long*)(bp + k * 128 + 64);
        unsigned long long b3 = *(const unsigned long long*)(bp + k * 128 + 96);
#pragma unroll
        for (int j = 0; j < 8; j++) {
            f2fma(acc[j][0], a2[j], b0);
            f2fma(acc[j][1], a2[j], b1);
            f2fma(acc[j][2], a2[j], b2);
            f2fma(acc[j][3], a2[j], b3);
        }
    }
}

#define NODE_SMEM_FLOATS (24960 + 24576)
#define NODE_SMEM_BYTES  (NODE_SMEM_FLOATS * 4)

__global__ void __launch_bounds__(256, 1)
node_kernel(const float* __restrict__ h,
            const float* __restrict__ Wn1, const float* __restrict__ bn1,
            const float* __restrict__ Wn2, const float* __restrict__ bn2,
            float* __restrict__ out) {
    extern __shared__ float sm[];
    float* As = sm;
    float* Bs = As + 24960;
    const int tid = threadIdx.x;
    const int tx = tid & 15, ty = tid >> 4;
    const int n0 = blockIdx.x * 128;

    {
        int r = tid >> 1, part = tid & 1;
        int n = n0 + r;
        int nc = (n < NN) ? n : (NN - 1);
        const float4* hr = (const float4*)h + (size_t)nc * 16 + part * 8;
#pragma unroll
        for (int q = 0; q < 8; q++) {
            float4 f = hr[q];
            int k0 = part * 32 + q * 4;
            As[(k0 + 0) * LDA + r] = f.x; As[(k0 + 1) * LDA + r] = f.y;
            As[(k0 + 2) * LDA + r] = f.z; As[(k0 + 3) * LDA + r] = f.w;
        }
        const float4* ar = (const float4*)g_aggr + (size_t)nc * 32 + part * 16;
#pragma unroll
        for (int q = 0; q < 16; q++) {
            float4 f = ar[q];
            int k0 = 64 + part * 64 + q * 4;
            As[(k0 + 0) * LDA + r] = f.x; As[(k0 + 1) * LDA + r] = f.y;
            As[(k0 + 2) * LDA + r] = f.z; As[(k0 + 3) * LDA + r] = f.w;
        }
    }
    for (int i4 = tid; i4 < (192 * 128) / 4; i4 += 256)
        ((float4*)Bs)[i4] = ((const float4*)Wn1)[i4];
    __syncthreads();

    unsigned long long acc[8][4];
    gemm128n(As, Bs, bn1, 192, ty, tx, acc);
    __syncthreads();
#pragma unroll
    for (int j = 0; j < 8; j++) {
        int r = ty * 8 + j;
#pragma unroll
        for (int i = 0; i < 4; i++) {
            float2 tt = up2(acc[j][i]);
            int cc = i * 32 + tx * 2;
            As[(cc + 0) * LDA + r] = silu_f(tt.x);
            As[(cc + 1) * LDA + r] = silu_f(tt.y);
        }
    }
    for (int i4 = tid; i4 < (128 * 64) / 4; i4 += 256)
        ((float4*)Bs)[i4] = ((const float4*)Wn2)[i4];
    __syncthreads();

    unsigned long long a2b[8][2];
    {
        const int c0 = tx * 2;
#pragma unroll
        for (int i = 0; i < 2; i++) {
            unsigned long long bi = pk2(bn2[i * 32 + c0], bn2[i * 32 + c0 + 1]);
#pragma unroll
            for (int j = 0; j < 8; j++) a2b[j][i] = bi;
        }
        const float* ap = As + ty * 8;
        const float* bp = Bs + c0;
#pragma unroll 2
        for (int k = 0; k < 128; k++) {
            float2 aA = *(const float2*)(ap + k * LDA + 0);
            float2 aB = *(const float2*)(ap + k * LDA + 2);
            float2 aC = *(const float2*)(ap + k * LDA + 4);
            float2 aD = *(const float2*)(ap + k * LDA + 6);
            unsigned long long a2[8];
            a2[0] = pk2(aA.x, aA.x); a2[1] = pk2(aA.y, aA.y);
            a2[2] = pk2(aB.x, aB.x); a2[3] = pk2(aB.y, aB.y);
            a2[4] = pk2(aC.x, aC.x); a2[5] = pk2(aC.y, aC.y);
            a2[6] = pk2(aD.x, aD.x); a2[7] = pk2(aD.y, aD.y);
            unsigned long long b0 = *(const unsigned long long*)(bp + k * 64 + 0);
            unsigned long long b1 = *(const unsigned long long*)(bp + k * 64 + 32);
#pragma unroll
            for (int j = 0; j < 8; j++) {
                f2fma(a2b[j][0], a2[j], b0);
                f2fma(a2b[j][1], a2[j], b1);
            }
        }
    }
#pragma unroll
    for (int j = 0; j < 8; j++) {
        int n = n0 + ty * 8 + j;
        if (n < NN) {
#pragma unroll
            for (int i = 0; i < 2; i++) {
                int cc = i * 32 + tx * 2;
                float2 hv = *(const float2*)(h + (size_t)n * 64 + cc);
                float2 tt = up2(a2b[j][i]);
                float2 o; o.x = hv.x + tt.x; o.y = hv.y + tt.y;
                *(float2*)(out + (size_t)n * 64 + cc) = o;
            }
        }
    }
}

// ---------------- launch ----------------
extern "C" void kernel_launch(void* const* d_in, const int* in_sizes, int n_in,
                              void* d_out, int out_size) {
    const float* h   = (const float*)d_in[0];
    const float* x   = (const float*)d_in[1];
    const float* v   = (const float*)d_in[2];
    const int*   ei  = (const int*)d_in[3];
    const float* ea  = (const float*)d_in[4];
    const float* Wm1 = (const float*)d_in[5];
    const float* bm1 = (const float*)d_in[6];
    const float* Wm2 = (const float*)d_in[7];
    const float* bm2 = (const float*)d_in[8];
    const float* Wn1 = (const float*)d_in[9];
    const float* bn1 = (const float*)d_in[10];
    const float* Wn2 = (const float*)d_in[11];
    const float* bn2 = (const float*)d_in[12];
    const float* Wc1 = (const float*)d_in[13];
    const float* bc1 = (const float*)d_in[14];
    const float* Wc2 = (const float*)d_in[15];
    const float* bc2 = (const float*)d_in[16];
    const float* Wv1 = (const float*)d_in[17];
    const float* bv1 = (const float*)d_in[18];
    const float* Wv2 = (const float*)d_in[19];
    const float* bv2 = (const float*)d_in[20];
    float* out = (float*)d_out;

    cudaFuncSetAttribute(edge_mma_kernel, cudaFuncAttributeMaxDynamicSharedMemorySize, EDGE_SMEM_BYTES);
    cudaFuncSetAttribute(node_kernel, cudaFuncAttributeMaxDynamicSharedMemorySize, NODE_SMEM_BYTES);

    init_kernel<<<2048, 256>>>(x, v, out);
    edge_mma_kernel<<<EE / 128, 256, EDGE_SMEM_BYTES>>>(
        h, x, ei, ea, Wm1, bm1, Wm2, bm2, Wc1, bc1, Wc2, bc2, Wv1, bv1, Wv2, bv2,
        out + (size_t)NN * 64, out + (size_t)NN * 64 + (size_t)NN * 3);
    node_kernel<<<(NN + 127) / 128, 256, NODE_SMEM_BYTES>>>(h, Wn1, bn1, Wn2, bn2, out);
}

// round 10
// speedup vs baseline: 3.5646x; 2.1649x over previous
#include <cuda_runtime.h>
#include <cstdint>

#define NN 100000
#define EE 1600000
#define LKA2 84    // As row stride in bf16-pairs (uint32): 84 mod 32 = 20 -> conflict-free A frags
#define LKB2 136   // Bs row stride in uint32: 136 mod 32 = 8 -> conflict-free B frags
#define LDA 130    // node-kernel transposed stride (proven)

// ---------------- global scratch ----------------
__device__ float g_aggr[(size_t)NN * 128];

// ---------------- helpers ----------------
__device__ __forceinline__ float silu_f(float v) {
    return v / (1.0f + __expf(-v));
}
// pack 2 floats -> bf16x2 (lo = first arg). PTX: first src operand -> HIGH half.
__device__ __forceinline__ uint32_t pkbf2(float lo, float hi) {
    uint32_t r; asm("cvt.rn.bf16x2.f32 %0, %1, %2;" : "=r"(r) : "f"(hi), "f"(lo)); return r;
}
__device__ __forceinline__ unsigned long long pk2(float lo, float hi) {
    unsigned long long r; asm("mov.b64 %0, {%1, %2};" : "=l"(r) : "f"(lo), "f"(hi)); return r;
}
__device__ __forceinline__ float2 up2(unsigned long long v) {
    float2 r; asm("mov.b64 {%0, %1}, %2;" : "=f"(r.x), "=f"(r.y) : "l"(v)); return r;
}
__device__ __forceinline__ void f2fma(unsigned long long& d, unsigned long long a, unsigned long long b) {
    asm("fma.rn.f32x2 %0, %1, %2, %0;" : "+l"(d) : "l"(a), "l"(b));
}
// bf16 tensor-core mma m16n8k16 (sm_80 baseline -> compiles at target sm_103)
__device__ __forceinline__ void mma16(float c[4], const uint32_t a[4], uint32_t b0, uint32_t b1) {
    asm volatile("mma.sync.aligned.m16n8k16.row.col.f32.bf16.bf16.f32 "
                 "{%0,%1,%2,%3}, {%4,%5,%6,%7}, {%8,%9}, {%0,%1,%2,%3};"
                 : "+f"(c[0]), "+f"(c[1]), "+f"(c[2]), "+f"(c[3])
                 : "r"(a[0]), "r"(a[1]), "r"(a[2]), "r"(a[3]), "r"(b0), "r"(b1));
}

// ---------------- init ----------------
__global__ void init_kernel(const float* __restrict__ x, const float* __restrict__ v,
                            float* __restrict__ out) {
    int idx = blockIdx.x * blockDim.x + threadIdx.x;
    int stride = gridDim.x * blockDim.x;
    for (int k = idx; k < NN * 128; k += stride) g_aggr[k] = 0.f;
    for (int k = idx; k < NN * 3; k += stride) {
        out[(size_t)NN * 64 + k] = x[k];
        out[(size_t)NN * 64 + (size_t)NN * 3 + k] = v[k];
    }
}

// ---------------- edge kernel pieces ----------------

// W [realK][128] row-major f32 -> Bs2[pair][n] bf16x2 (lo = even k), zero-padded
__device__ __forceinline__ void load_B(uint32_t* __restrict__ Bs2, const float* __restrict__ W,
                                       int pairs, int realK, int tid) {
    for (int idx = tid; idx < pairs * 128; idx += 256) {
        int p = idx >> 7, n = idx & 127;
        float lo = (2 * p < realK) ? W[(2 * p) * 128 + n] : 0.f;
        float hi = (2 * p + 1 < realK) ? W[(2 * p + 1) * 128 + n] : 0.f;
        Bs2[p * LKB2 + n] = pkbf2(lo, hi);
    }
}

// warp GEMM: rows [rw0,rw0+32), cols [cn0,cn0+64); bias folded into c init
__device__ __forceinline__ void warp_gemm(const uint32_t* __restrict__ As2,
                                          const uint32_t* __restrict__ Bs2,
                                          const float* __restrict__ bias,
                                          int KB, int rw0, int cn0, int g, int t,
                                          float c[2][8][4]) {
#pragma unroll
    for (int nt = 0; nt < 8; nt++) {
        float b0v = bias[cn0 + nt * 8 + 2 * t];
        float b1v = bias[cn0 + nt * 8 + 2 * t + 1];
        c[0][nt][0] = b0v; c[0][nt][1] = b1v; c[0][nt][2] = b0v; c[0][nt][3] = b1v;
        c[1][nt][0] = b0v; c[1][nt][1] = b1v; c[1][nt][2] = b0v; c[1][nt][3] = b1v;
    }
#pragma unroll 1
    for (int kb = 0; kb < KB; kb++) {
        uint32_t a[2][4];
#pragma unroll
        for (int mh = 0; mh < 2; mh++) {
            const uint32_t* p0 = As2 + (rw0 + mh * 16 + g) * LKA2 + kb * 8 + t;
            const uint32_t* p1 = p0 + 8 * LKA2;
            a[mh][0] = p0[0];   // row g,   k-pair t
            a[mh][1] = p1[0];   // row g+8, k-pair t
            a[mh][2] = p0[4];   // row g,   k-pair t+4
            a[mh][3] = p1[4];   // row g+8, k-pair t+4
        }
#pragma unroll
        for (int nt = 0; nt < 8; nt++) {
            uint32_t b0 = Bs2[(kb * 8 + t) * LKB2 + cn0 + nt * 8 + g];
            uint32_t b1 = Bs2[(kb * 8 + 4 + t) * LKB2 + cn0 + nt * 8 + g];
            mma16(c[0][nt], a[0], b0, b1);
            mma16(c[1][nt], a[1], b0, b1);
        }
    }
}

// silu(c) -> As2 bf16 pairs (own row stripe); optionally also red.global f32 msg aggregation
__device__ __forceinline__ void store_act(uint32_t* __restrict__ As2, float c[2][8][4],
                                          const int* __restrict__ srow, bool do_red,
                                          int rw0, int cn0, int g, int t) {
#pragma unroll
    for (int mh = 0; mh < 2; mh++) {
        int r0 = rw0 + mh * 16 + g;
        int pbase = (cn0 >> 1);
#pragma unroll
        for (int nt = 0; nt < 8; nt++) {
            int pidx = pbase + nt * 4 + t;
            float v0 = silu_f(c[mh][nt][0]);
            float v1 = silu_f(c[mh][nt][1]);
            float v2 = silu_f(c[mh][nt][2]);
            float v3 = silu_f(c[mh][nt][3]);
            As2[r0 * LKA2 + pidx] = pkbf2(v0, v1);
            As2[(r0 + 8) * LKA2 + pidx] = pkbf2(v2, v3);
            if (do_red) {
                int col = cn0 + nt * 8 + 2 * t;
                float* d0 = g_aggr + (size_t)srow[r0] * 128 + col;
                float* d1 = g_aggr + (size_t)srow[r0 + 8] * 128 + col;
                asm volatile("red.global.add.v2.f32 [%0], {%1,%2};" :: "l"(d0), "f"(v0), "f"(v1) : "memory");
                asm volatile("red.global.add.v2.f32 [%0], {%1,%2};" :: "l"(d1), "f"(v2), "f"(v3) : "memory");
            }
        }
    }
}

// row-dot with w2 after silu, quad-reduce, stage per-row sums
__device__ __forceinline__ void reduce_rows(float c[2][8][4], const float* __restrict__ w2,
                                            float* __restrict__ sredh,
                                            int rw0, int cn0, int g, int t) {
#pragma unroll
    for (int mh = 0; mh < 2; mh++) {
        float s0 = 0.f, s1 = 0.f;
#pragma unroll
        for (int nt = 0; nt < 8; nt++) {
            int col = cn0 + nt * 8 + 2 * t;
            float w0 = w2[col], w1 = w2[col + 1];
            s0 += silu_f(c[mh][nt][0]) * w0 + silu_f(c[mh][nt][1]) * w1;
            s1 += silu_f(c[mh][nt][2]) * w0 + silu_f(c[mh][nt][3]) * w1;
        }
        s0 += __shfl_xor_sync(0xffffffffu, s0, 1);
        s0 += __shfl_xor_sync(0xffffffffu, s0, 2);
        s1 += __shfl_xor_sync(0xffffffffu, s1, 1);
        s1 += __shfl_xor_sync(0xffffffffu, s1, 2);
        if (t == 0) {
            sredh[rw0 + mh * 16 + g] = s0;
            sredh[rw0 + mh * 16 + g + 8] = s1;
        }
    }
}

// SMEM (uint32 units): As2 10752 | Bs2 9792 | sbias 768 | ssq 128 | srel 384 | sredp 128 | sredq 128 | srow 128 | scol 128
#define EDGE_SMEM_U32  (10752 + 9792 + 768 + 128 + 384 + 128 + 128 + 128 + 128)
#define EDGE_SMEM_BYTES (EDGE_SMEM_U32 * 4)   // 89344 -> 2 CTAs/SM

__global__ void __launch_bounds__(256, 2)
edge_mma_kernel(const float* __restrict__ h, const float* __restrict__ x,
                const int* __restrict__ ei, const float* __restrict__ ea,
                const float* __restrict__ Wm1, const float* __restrict__ bm1,
                const float* __restrict__ Wm2, const float* __restrict__ bm2,
                const float* __restrict__ Wc1, const float* __restrict__ bc1,
                const float* __restrict__ Wc2, const float* __restrict__ bc2,
                const float* __restrict__ Wv1, const float* __restrict__ bv1,
                const float* __restrict__ Wv2, const float* __restrict__ bv2,
                float* __restrict__ outx, float* __restrict__ outv) {
    extern __shared__ uint32_t smu[];
    uint32_t* As2  = smu;                 // 10752
    uint32_t* Bs2  = As2 + 10752;         // 9792
    float* sbias   = (float*)(Bs2 + 9792);   // 768: bm1|bm2|bc1|bv1|Wc2|Wv2
    float* ssq     = sbias + 768;         // 128
    float* srel    = ssq + 128;           // 384
    float* sredp   = srel + 384;          // 128
    float* sredq   = sredp + 128;         // 128
    int*   srow    = (int*)(sredq + 128); // 128
    int*   scol    = srow + 128;          // 128

    const int tid = threadIdx.x;
    const int w = tid >> 5, lane = tid & 31;
    const int g = lane >> 2, t = lane & 3;
    const int rw0 = (w & 3) * 32, cn0 = (w >> 2) * 64;
    const int e0 = blockIdx.x * 128;

    // ---- phase 0: metadata (tid<128) + bias staging (tid>=128) ----
    if (tid < 128) {
        int e = e0 + tid;
        int r = ei[e], cc = ei[EE + e];
        srow[tid] = r; scol[tid] = cc;
        float dx = x[r * 3 + 0] - x[cc * 3 + 0];
        float dy = x[r * 3 + 1] - x[cc * 3 + 1];
        float dz = x[r * 3 + 2] - x[cc * 3 + 2];
        float sq = dx * dx + dy * dy + dz * dz;
        ssq[tid] = sq;
        srel[tid * 3 + 0] = dx; srel[tid * 3 + 1] = dy; srel[tid * 3 + 2] = dz;
        float4 ea0 = ((const float4*)(ea + (size_t)e * 8))[0];
        float4 ea1 = ((const float4*)(ea + (size_t)e * 8))[1];
        uint32_t* dst = As2 + tid * LKA2 + 64;   // feature pairs 64..71
        dst[0] = pkbf2(sq, dz);
        dst[1] = pkbf2(ea0.x, ea0.y);
        dst[2] = pkbf2(ea0.z, ea0.w);
        dst[3] = pkbf2(ea1.x, ea1.y);
        dst[4] = pkbf2(ea1.z, ea1.w);
        dst[5] = 0u; dst[6] = 0u; dst[7] = 0u;
    } else {
        for (int i = tid - 128; i < 768; i += 128) {
            int j = i & 127, gg = i >> 7;
            sbias[i] = (gg == 0) ? bm1[j] : (gg == 1) ? bm2[j] : (gg == 2) ? bc1[j] :
                       (gg == 3) ? bv1[j] : (gg == 4) ? Wc2[j] : Wv2[j];
        }
    }
    __syncthreads();

    // ---- gather h rows (bf16 pairs) + load Wm1 ----
    {
        int r = tid >> 1, part = tid & 1;
        int node = part ? scol[r] : srow[r];
        const float4* hp = (const float4*)(h + (size_t)node * 64);
        uint32_t* dst = As2 + r * LKA2 + part * 32;
#pragma unroll
        for (int q = 0; q < 16; q++) {
            float4 f = hp[q];
            dst[q * 2 + 0] = pkbf2(f.x, f.y);
            dst[q * 2 + 1] = pkbf2(f.z, f.w);
        }
    }
    load_B(Bs2, Wm1, 72, 138, tid);
    __syncthreads();

    float c[2][8][4];

    // ---- GEMM1: msg_in @ Wm1 + bm1 -> H1 = silu ----
    warp_gemm(As2, Bs2, sbias + 0, 9, rw0, cn0, g, t, c);
    store_act(As2, c, srow, false, rw0, cn0, g, t);
    __syncthreads();
    load_B(Bs2, Wm2, 64, 128, tid);
    __syncthreads();

    // ---- GEMM2: H1 @ Wm2 + bm2 -> msg = silu; red-aggregate f32 + bf16 into As ----
    warp_gemm(As2, Bs2, sbias + 128, 8, rw0, cn0, g, t, c);
    store_act(As2, c, srow, true, rw0, cn0, g, t);
    __syncthreads();
    load_B(Bs2, Wc1, 64, 128, tid);
    __syncthreads();

    // ---- GEMM3: msg @ Wc1 + bc1 -> x-weights ----
    warp_gemm(As2, Bs2, sbias + 256, 8, rw0, cn0, g, t, c);
    reduce_rows(c, sbias + 512, (w >> 2) ? sredq : sredp, rw0, cn0, g, t);
    __syncthreads();
    if (tid < 128) {
        float tot = sredp[tid] + sredq[tid] + bc2[0];
        float wv = __fdividef(tot, ssq[tid] + 1e-8f);
        int rw = srow[tid];
        atomicAdd(outx + (size_t)rw * 3 + 0, srel[tid * 3 + 0] * wv);
        atomicAdd(outx + (size_t)rw * 3 + 1, srel[tid * 3 + 1] * wv);
        atomicAdd(outx + (size_t)rw * 3 + 2, srel[tid * 3 + 2] * wv);
    }
    load_B(Bs2, Wv1, 64, 128, tid);
    __syncthreads();

    // ---- GEMM4: msg @ Wv1 + bv1 -> v-weights ----
    warp_gemm(As2, Bs2, sbias + 384, 8, rw0, cn0, g, t, c);
    reduce_rows(c, sbias + 640, (w >> 2) ? sredq : sredp, rw0, cn0, g, t);
    __syncthreads();
    if (tid < 128) {
        float tot = sredp[tid] + sredq[tid] + bv2[0];
        float wv = __fdividef(tot, ssq[tid] + 1e-8f);
        int rw = srow[tid];
        atomicAdd(outv + (size_t)rw * 3 + 0, srel[tid * 3 + 0] * wv);
        atomicAdd(outv + (size_t)rw * 3 + 1, srel[tid * 3 + 1] * wv);
        atomicAdd(outv + (size_t)rw * 3 + 2, srel[tid * 3 + 2] * wv);
    }
}

// ---------------- node kernel (FFMA2, proven) ----------------
__device__ __forceinline__ void gemm128n(const float* __restrict__ As_,
                                         const float* __restrict__ Bs_,
                                         const float* __restrict__ bias,
                                         int K, int ty, int tx,
                                         unsigned long long acc[8][4]) {
    const int c0 = tx * 2;
#pragma unroll
    for (int i = 0; i < 4; i++) {
        unsigned long long bi = pk2(bias[i * 32 + c0], bias[i * 32 + c0 + 1]);
#pragma unroll
        for (int j = 0; j < 8; j++) acc[j][i] = bi;
    }
    const float* ap = As_ + ty * 8;
    const float* bp = Bs_ + c0;
#pragma unroll 2
    for (int k = 0; k < K; k++) {
        float2 aA = *(const float2*)(ap + k * LDA + 0);
        float2 aB = *(const float2*)(ap + k * LDA + 2);
        float2 aC = *(const float2*)(ap + k * LDA + 4);
        float2 aD = *(const float2*)(ap + k * LDA + 6);
        unsigned long long a2[8];
        a2[0] = pk2(aA.x, aA.x); a2[1] = pk2(aA.y, aA.y);
        a2[2] = pk2(aB.x, aB.x); a2[3] = pk2(aB.y, aB.y);
        a2[4] = pk2(aC.x, aC.x); a2[5] = pk2(aC.y, aC.y);
        a2[6] = pk2(aD.x, aD.x); a2[7] = pk2(aD.y, aD.y);
        unsigned long long b0 = *(const unsigned long long*)(bp + k * 128 + 0);
        unsigned long long b1 = *(const unsigned long long*)(bp + k * 128 + 32);
        unsigned long long b2 = *(const unsigned long long*)(bp + k * 128 + 64);
        unsigned long long b3 = *(const unsigned long long*)(bp + k * 128 + 96);
#pragma unroll
        for (int j = 0; j < 8; j++) {
            f2fma(acc[j][0], a2[j], b0);
            f2fma(acc[j][1], a2[j], b1);
            f2fma(acc[j][2], a2[j], b2);
            f2fma(acc[j][3], a2[j], b3);
        }
    }
}

#define NODE_SMEM_FLOATS (24960 + 24576)
#define NODE_SMEM_BYTES  (NODE_SMEM_FLOATS * 4)

__global__ void __launch_bounds__(256, 1)
node_kernel(const float* __restrict__ h,
            const float* __restrict__ Wn1, const float* __restrict__ bn1,
            const float* __restrict__ Wn2, const float* __restrict__ bn2,
            float* __restrict__ out) {
    extern __shared__ float sm[];
    float* As = sm;
    float* Bs = As + 24960;
    const int tid = threadIdx.x;
    const int tx = tid & 15, ty = tid >> 4;
    const int n0 = blockIdx.x * 128;

    {
        int r = tid >> 1, part = tid & 1;
        int n = n0 + r;
        int nc = (n < NN) ? n : (NN - 1);
        const float4* hr = (const float4*)h + (size_t)nc * 16 + part * 8;
#pragma unroll
        for (int q = 0; q < 8; q++) {
            float4 f = hr[q];
            int k0 = part * 32 + q * 4;
            As[(k0 + 0) * LDA + r] = f.x; As[(k0 + 1) * LDA + r] = f.y;
            As[(k0 + 2) * LDA + r] = f.z; As[(k0 + 3) * LDA + r] = f.w;
        }
        const float4* ar = (const float4*)g_aggr + (size_t)nc * 32 + part * 16;
#pragma unroll
        for (int q = 0; q < 16; q++) {
            float4 f = ar[q];
            int k0 = 64 + part * 64 + q * 4;
            As[(k0 + 0) * LDA + r] = f.x; As[(k0 + 1) * LDA + r] = f.y;
            As[(k0 + 2) * LDA + r] = f.z; As[(k0 + 3) * LDA + r] = f.w;
        }
    }
    for (int i4 = tid; i4 < (192 * 128) / 4; i4 += 256)
        ((float4*)Bs)[i4] = ((const float4*)Wn1)[i4];
    __syncthreads();

    unsigned long long acc[8][4];
    gemm128n(As, Bs, bn1, 192, ty, tx, acc);
    __syncthreads();
#pragma unroll
    for (int j = 0; j < 8; j++) {
        int r = ty * 8 + j;
#pragma unroll
        for (int i = 0; i < 4; i++) {
            float2 tt = up2(acc[j][i]);
            int cc = i * 32 + tx * 2;
            As[(cc + 0) * LDA + r] = silu_f(tt.x);
            As[(cc + 1) * LDA + r] = silu_f(tt.y);
        }
    }
    for (int i4 = tid; i4 < (128 * 64) / 4; i4 += 256)
        ((float4*)Bs)[i4] = ((const float4*)Wn2)[i4];
    __syncthreads();

    unsigned long long a2b[8][2];
    {
        const int c0 = tx * 2;
#pragma unroll
        for (int i = 0; i < 2; i++) {
            unsigned long long bi = pk2(bn2[i * 32 + c0], bn2[i * 32 + c0 + 1]);
#pragma unroll
            for (int j = 0; j < 8; j++) a2b[j][i] = bi;
        }
        const float* ap = As + ty * 8;
        const float* bp = Bs + c0;
#pragma unroll 2
        for (int k = 0; k < 128; k++) {
            float2 aA = *(const float2*)(ap + k * LDA + 0);
            float2 aB = *(const float2*)(ap + k * LDA + 2);
            float2 aC = *(const float2*)(ap + k * LDA + 4);
            float2 aD = *(const float2*)(ap + k * LDA + 6);
            unsigned long long a2[8];
            a2[0] = pk2(aA.x, aA.x); a2[1] = pk2(aA.y, aA.y);
            a2[2] = pk2(aB.x, aB.x); a2[3] = pk2(aB.y, aB.y);
            a2[4] = pk2(aC.x, aC.x); a2[5] = pk2(aC.y, aC.y);
            a2[6] = pk2(aD.x, aD.x); a2[7] = pk2(aD.y, aD.y);
            unsigned long long b0 = *(const unsigned long long*)(bp + k * 64 + 0);
            unsigned long long b1 = *(const unsigned long long*)(bp + k * 64 + 32);
#pragma unroll
            for (int j = 0; j < 8; j++) {
                f2fma(a2b[j][0], a2[j], b0);
                f2fma(a2b[j][1], a2[j], b1);
            }
        }
    }
#pragma unroll
    for (int j = 0; j < 8; j++) {
        int n = n0 + ty * 8 + j;
        if (n < NN) {
#pragma unroll
            for (int i = 0; i < 2; i++) {
                int cc = i * 32 + tx * 2;
                float2 hv = *(const float2*)(h + (size_t)n * 64 + cc);
                float2 tt = up2(a2b[j][i]);
                float2 o; o.x = hv.x + tt.x; o.y = hv.y + tt.y;
                *(float2*)(out + (size_t)n * 64 + cc) = o;
            }
        }
    }
}

// ---------------- launch ----------------
extern "C" void kernel_launch(void* const* d_in, const int* in_sizes, int n_in,
                              void* d_out, int out_size) {
    const float* h   = (const float*)d_in[0];
    const float* x   = (const float*)d_in[1];
    const float* v   = (const float*)d_in[2];
    const int*   ei  = (const int*)d_in[3];
    const float* ea  = (const float*)d_in[4];
    const float* Wm1 = (const float*)d_in[5];
    const float* bm1 = (const float*)d_in[6];
    const float* Wm2 = (const float*)d_in[7];
    const float* bm2 = (const float*)d_in[8];
    const float* Wn1 = (const float*)d_in[9];
    const float* bn1 = (const float*)d_in[10];
    const float* Wn2 = (const float*)d_in[11];
    const float* bn2 = (const float*)d_in[12];
    const float* Wc1 = (const float*)d_in[13];
    const float* bc1 = (const float*)d_in[14];
    const float* Wc2 = (const float*)d_in[15];
    const float* bc2 = (const float*)d_in[16];
    const float* Wv1 = (const float*)d_in[17];
    const float* bv1 = (const float*)d_in[18];
    const float* Wv2 = (const float*)d_in[19];
    const float* bv2 = (const float*)d_in[20];
    float* out = (float*)d_out;

    cudaFuncSetAttribute(edge_mma_kernel, cudaFuncAttributeMaxDynamicSharedMemorySize, EDGE_SMEM_BYTES);
    cudaFuncSetAttribute(node_kernel, cudaFuncAttributeMaxDynamicSharedMemorySize, NODE_SMEM_BYTES);

    init_kernel<<<2048, 256>>>(x, v, out);
    edge_mma_kernel<<<EE / 128, 256, EDGE_SMEM_BYTES>>>(
        h, x, ei, ea, Wm1, bm1, Wm2, bm2, Wc1, bc1, Wc2, bc2, Wv1, bv1, Wv2, bv2,
        out + (size_t)NN * 64, out + (size_t)NN * 64 + (size_t)NN * 3);
    node_kernel<<<(NN + 127) / 128, 256, NODE_SMEM_BYTES>>>(h, Wn1, bn1, Wn2, bn2, out);
}

// round 13
// speedup vs baseline: 4.0385x; 1.1330x over previous
#include <cuda_runtime.h>
#include <cstdint>

#define NN 100000
#define EE 1600000
#define LKA2 76    // As row stride (u32 pairs): 76 mod 32 = 12 -> 2-wavefront v2 frags
#define LKB2 76    // BsT row stride (u32 pairs), same property
#define LDA 130    // node-kernel transposed stride (proven)

// ---------------- global scratch ----------------
__device__ float    g_aggr[(size_t)NN * 128];
__device__ uint32_t g_wimg[4 * 9728];   // bf16x2 images: Wm1|Wm2|Wc1|Wv1, layout [col][slot] = smem BsT

// ---------------- helpers ----------------
__device__ __forceinline__ float silu_f(float v) {          // exact
    return v / (1.0f + __expf(-v));
}
__device__ __forceinline__ float silu_t(float v) {          // 1-MUFU tanh version (bf16-bound outputs only)
    float t; asm("tanh.approx.f32 %0, %1;" : "=f"(t) : "f"(v * 0.5f));
    return fmaf(v * 0.5f, t, v * 0.5f);
}
// pack 2 floats -> bf16x2 (lo = first arg). PTX: first src -> HIGH half.
__device__ __forceinline__ uint32_t pkbf2(float lo, float hi) {
    uint32_t r; asm("cvt.rn.bf16x2.f32 %0, %1, %2;" : "=r"(r) : "f"(hi), "f"(lo)); return r;
}
__device__ __forceinline__ unsigned long long pk2(float lo, float hi) {
    unsigned long long r; asm("mov.b64 %0, {%1, %2};" : "=l"(r) : "f"(lo), "f"(hi)); return r;
}
__device__ __forceinline__ float2 up2(unsigned long long v) {
    float2 r; asm("mov.b64 {%0, %1}, %2;" : "=f"(r.x), "=f"(r.y) : "l"(v)); return r;
}
__device__ __forceinline__ void f2fma(unsigned long long& d, unsigned long long a, unsigned long long b) {
    asm("fma.rn.f32x2 %0, %1, %2, %0;" : "+l"(d) : "l"(a), "l"(b));
}
__device__ __forceinline__ void mma16(float c[4], const uint32_t a[4], uint32_t b0, uint32_t b1) {
    asm volatile("mma.sync.aligned.m16n8k16.row.col.f32.bf16.bf16.f32 "
                 "{%0,%1,%2,%3}, {%4,%5,%6,%7}, {%8,%9}, {%0,%1,%2,%3};"
                 : "+f"(c[0]), "+f"(c[1]), "+f"(c[2]), "+f"(c[3])
                 : "r"(a[0]), "r"(a[1]), "r"(a[2]), "r"(a[3]), "r"(b0), "r"(b1));
}
__device__ __forceinline__ uint32_t smem_u32(const void* p) {
    uint32_t a;
    asm("{ .reg .u64 t; cvta.to.shared.u64 t, %1; cvt.u32.u64 %0, t; }" : "=r"(a) : "l"(p));
    return a;
}
__device__ __forceinline__ void cp16(uint32_t saddr, const void* g) {
    asm volatile("cp.async.cg.shared.global [%0], [%1], 16;" :: "r"(saddr), "l"(g) : "memory");
}
#define CP_COMMIT() asm volatile("cp.async.commit_group;" ::: "memory")
#define CP_WAIT0()  asm volatile("cp.async.wait_group 0;" ::: "memory")

// k-pair interleave: logical pair p -> physical slot (pairs t and t+4 adjacent).
// VALID ONLY for full groups of 8 (p's group fully populated); callers keep p < 72.
__device__ __forceinline__ int physp(int p) {
    return (p & ~7) | ((p & 3) << 1) | ((p >> 2) & 1);
}

// ---------------- prep: bf16x2 interleaved-transposed weight images ----------------
__global__ void prep_kernel(const float* __restrict__ Wm1, const float* __restrict__ Wm2,
                            const float* __restrict__ Wc1, const float* __restrict__ Wv1) {
    int idx = blockIdx.x * blockDim.x + threadIdx.x;
    if (idx >= 4 * 9728) return;
    int img = idx / 9728;
    int r = idx - img * 9728;
    int n = r / 76;           // output col 0..127
    int kr = r - n * 76;      // logical k-pair 0..75
    // FIX (R11 bug): stride 76 is not a multiple of 8, so physp() on the partial
    // tail group 72..75 maps OUT OF RANGE (76,78) and clobbers column n+1's
    // slots 0/2 with zeros. Slots >=72 are never read by any GEMM -> skip them.
    if (kr >= 72) return;
    const float* W = (img == 0) ? Wm1 : (img == 1) ? Wm2 : (img == 2) ? Wc1 : Wv1;
    int realK = (img == 0) ? 138 : 128;
    float lo = (2 * kr < realK) ? W[(2 * kr) * 128 + n] : 0.f;
    float hi = (2 * kr + 1 < realK) ? W[(2 * kr + 1) * 128 + n] : 0.f;
    g_wimg[img * 9728 + n * 76 + physp(kr)] = pkbf2(lo, hi);
}

// ---------------- init ----------------
__global__ void init_kernel(const float* __restrict__ x, const float* __restrict__ v,
                            float* __restrict__ out) {
    int idx = blockIdx.x * blockDim.x + threadIdx.x;
    int stride = gridDim.x * blockDim.x;
    for (int k = idx; k < NN * 128; k += stride) g_aggr[k] = 0.f;
    for (int k = idx; k < NN * 3; k += stride) {
        out[(size_t)NN * 64 + k] = x[k];
        out[(size_t)NN * 64 + (size_t)NN * 3 + k] = v[k];
    }
}

// ---------------- edge kernel pieces ----------------

// async copy one full weight image (9728 u32 = 2432 x 16B) into BsT
__device__ __forceinline__ void load_B_async(uint32_t bsAddr, const uint32_t* __restrict__ gsrc, int tid) {
    for (int i = tid; i < 2432; i += 256)
        cp16(bsAddr + (uint32_t)i * 16u, (const char*)gsrc + (size_t)i * 16);
    CP_COMMIT();
}

// warp GEMM: rows [rw0,rw0+32), cols [cn0,cn0+64); bias folded into c init; v2 fragment loads
__device__ __forceinline__ void warp_gemm(const uint32_t* __restrict__ As2,
                                          const uint32_t* __restrict__ BsT,
                                          const float* __restrict__ bias,
                                          int KB, int rw0, int cn0, int g, int t,
                                          float c[2][8][4]) {
#pragma unroll
    for (int nt = 0; nt < 8; nt++) {
        float b0v = bias[cn0 + nt * 8 + 2 * t];
        float b1v = bias[cn0 + nt * 8 + 2 * t + 1];
        c[0][nt][0] = b0v; c[0][nt][1] = b1v; c[0][nt][2] = b0v; c[0][nt][3] = b1v;
        c[1][nt][0] = b0v; c[1][nt][1] = b1v; c[1][nt][2] = b0v; c[1][nt][3] = b1v;
    }
    const uint32_t* arow = As2 + (rw0 + g) * LKA2 + 2 * t;
    const uint32_t* brow = BsT + (cn0 + g) * LKB2 + 2 * t;
#pragma unroll 1
    for (int kb = 0; kb < KB; kb++) {
        uint2 a00 = *(const uint2*)(arow + kb * 8);                 // row r:    (k t, k t+4)
        uint2 a01 = *(const uint2*)(arow + 8 * LKA2 + kb * 8);      // row r+8
        uint2 a10 = *(const uint2*)(arow + 16 * LKA2 + kb * 8);     // row r+16
        uint2 a11 = *(const uint2*)(arow + 24 * LKA2 + kb * 8);     // row r+24
        uint32_t a0[4] = {a00.x, a01.x, a00.y, a01.y};
        uint32_t a1[4] = {a10.x, a11.x, a10.y, a11.y};
#pragma unroll
        for (int nt = 0; nt < 8; nt++) {
            uint2 b = *(const uint2*)(brow + (nt * 8) * LKB2 + kb * 8);
            mma16(c[0][nt], a0, b.x, b.y);
            mma16(c[1][nt], a1, b.x, b.y);
        }
    }
}

// silu(c) -> As2 bf16 pairs (interleaved slots); do_red: exact silu + f32 aggregation
__device__ __forceinline__ void store_act(uint32_t* __restrict__ As2, float c[2][8][4],
                                          const int* __restrict__ srow, bool do_red,
                                          int rw0, int cn0, int g, int t) {
#pragma unroll
    for (int mh = 0; mh < 2; mh++) {
        int r0 = rw0 + mh * 16 + g;
#pragma unroll
        for (int nt = 0; nt < 8; nt++) {
            int slot = (cn0 >> 1) + ((nt >> 1) << 3) + (t << 1) + (nt & 1);
            float v0, v1, v2, v3;
            if (do_red) {
                v0 = silu_f(c[mh][nt][0]); v1 = silu_f(c[mh][nt][1]);
                v2 = silu_f(c[mh][nt][2]); v3 = silu_f(c[mh][nt][3]);
            } else {
                v0 = silu_t(c[mh][nt][0]); v1 = silu_t(c[mh][nt][1]);
                v2 = silu_t(c[mh][nt][2]); v3 = silu_t(c[mh][nt][3]);
            }
            As2[r0 * LKA2 + slot] = pkbf2(v0, v1);
            As2[(r0 + 8) * LKA2 + slot] = pkbf2(v2, v3);
            if (do_red) {
                int col = cn0 + nt * 8 + 2 * t;
                float* d0 = g_aggr + (size_t)srow[r0] * 128 + col;
                float* d1 = g_aggr + (size_t)srow[r0 + 8] * 128 + col;
                asm volatile("red.global.add.v2.f32 [%0], {%1,%2};" :: "l"(d0), "f"(v0), "f"(v1) : "memory");
                asm volatile("red.global.add.v2.f32 [%0], {%1,%2};" :: "l"(d1), "f"(v2), "f"(v3) : "memory");
            }
        }
    }
}

// row-dot with w2 after silu (exact), quad-reduce, stage per-row sums
__device__ __forceinline__ void reduce_rows(float c[2][8][4], const float* __restrict__ w2,
                                            float* __restrict__ sredh,
                                            int rw0, int cn0, int g, int t) {
#pragma unroll
    for (int mh = 0; mh < 2; mh++) {
        float s0 = 0.f, s1 = 0.f;
#pragma unroll
        for (int nt = 0; nt < 8; nt++) {
            int col = cn0 + nt * 8 + 2 * t;
            float w0 = w2[col], w1 = w2[col + 1];
            s0 += silu_f(c[mh][nt][0]) * w0 + silu_f(c[mh][nt][1]) * w1;
            s1 += silu_f(c[mh][nt][2]) * w0 + silu_f(c[mh][nt][3]) * w1;
        }
        s0 += __shfl_xor_sync(0xffffffffu, s0, 1);
        s0 += __shfl_xor_sync(0xffffffffu, s0, 2);
        s1 += __shfl_xor_sync(0xffffffffu, s1, 1);
        s1 += __shfl_xor_sync(0xffffffffu, s1, 2);
        if (t == 0) {
            sredh[rw0 + mh * 16 + g] = s0;
            sredh[rw0 + mh * 16 + g + 8] = s1;
        }
    }
}

// SMEM (u32): As2 9728 | BsT 9728 | sbias 768 | ssq 128 | srel 384 | sredp 128 | sredq 128 | srow 128 | scol 128
#define EDGE_SMEM_U32  (9728 + 9728 + 768 + 128 + 384 + 128 + 128 + 128 + 128)
#define EDGE_SMEM_BYTES (EDGE_SMEM_U32 * 4)   // 84992 -> 2 CTAs/SM

__global__ void __launch_bounds__(256, 2)
edge_mma_kernel(const float* __restrict__ h, const float* __restrict__ x,
                const int* __restrict__ ei, const float* __restrict__ ea,
                const float* __restrict__ bm1, const float* __restrict__ bm2,
                const float* __restrict__ bc1, const float* __restrict__ bc2,
                const float* __restrict__ bv1, const float* __restrict__ bv2,
                const float* __restrict__ Wc2, const float* __restrict__ Wv2,
                float* __restrict__ outx, float* __restrict__ outv) {
    extern __shared__ uint32_t smu[];
    uint32_t* As2  = smu;                    // 9728
    uint32_t* BsT  = As2 + 9728;             // 9728
    float* sbias   = (float*)(BsT + 9728);   // 768: bm1|bm2|bc1|bv1|Wc2|Wv2
    float* ssq     = sbias + 768;            // 128
    float* srel    = ssq + 128;              // 384
    float* sredp   = srel + 384;             // 128
    float* sredq   = sredp + 128;            // 128
    int*   srow    = (int*)(sredq + 128);    // 128
    int*   scol    = srow + 128;             // 128

    const int tid = threadIdx.x;
    const int w = tid >> 5, lane = tid & 31;
    const int g = lane >> 2, t = lane & 3;
    const int rw0 = (w & 3) * 32, cn0 = (w >> 2) * 64;
    const int e0 = blockIdx.x * 128;
    const uint32_t bsAddr = smem_u32(BsT);

    // kick Wm1 copy immediately (overlaps metadata + gather)
    load_B_async(bsAddr, g_wimg + 0, tid);

    // ---- phase 0: metadata (tid<128) + bias staging (tid>=128) ----
    if (tid < 128) {
        int e = e0 + tid;
        int r = ei[e], cc = ei[EE + e];
        srow[tid] = r; scol[tid] = cc;
        float dx = x[r * 3 + 0] - x[cc * 3 + 0];
        float dy = x[r * 3 + 1] - x[cc * 3 + 1];
        float dz = x[r * 3 + 2] - x[cc * 3 + 2];
        float sq = dx * dx + dy * dy + dz * dz;
        ssq[tid] = sq;
        srel[tid * 3 + 0] = dx; srel[tid * 3 + 1] = dy; srel[tid * 3 + 2] = dz;
        float4 ea0 = ((const float4*)(ea + (size_t)e * 8))[0];
        float4 ea1 = ((const float4*)(ea + (size_t)e * 8))[1];
        uint32_t* dst = As2 + tid * LKA2 + 64;   // group 64..71, interleaved slots
        dst[0] = pkbf2(sq, dz);        // p64
        dst[2] = pkbf2(ea0.x, ea0.y);  // p65
        dst[4] = pkbf2(ea0.z, ea0.w);  // p66
        dst[6] = pkbf2(ea1.x, ea1.y);  // p67
        dst[1] = pkbf2(ea1.z, ea1.w);  // p68
        dst[3] = 0u; dst[5] = 0u; dst[7] = 0u;   // p69..71 zero pad
    } else {
        for (int i = tid - 128; i < 768; i += 128) {
            int j = i & 127, gg = i >> 7;
            sbias[i] = (gg == 0) ? bm1[j] : (gg == 1) ? bm2[j] : (gg == 2) ? bc1[j] :
                       (gg == 3) ? bv1[j] : (gg == 4) ? Wc2[j] : Wv2[j];
        }
    }
    __syncthreads();

    // ---- gather h rows (bf16 pairs, interleaved slots) ----
    {
        int r = tid >> 1, part = tid & 1;
        int node = part ? scol[r] : srow[r];
        const float4* hp = (const float4*)(h + (size_t)node * 64);
        uint32_t* dst = As2 + r * LKA2;
        int pb = part * 32;
#pragma unroll
        for (int q = 0; q < 16; q++) {
            float4 f = hp[q];
            dst[physp(pb + q * 2)]     = pkbf2(f.x, f.y);
            dst[physp(pb + q * 2 + 1)] = pkbf2(f.z, f.w);
        }
    }
    CP_WAIT0();
    __syncthreads();

    float c[2][8][4];

    // ---- GEMM1: msg_in @ Wm1 + bm1 ----
    warp_gemm(As2, BsT, sbias + 0, 9, rw0, cn0, g, t, c);
    __syncthreads();                                   // all reads of As/Bs done (race fix)
    load_B_async(bsAddr, g_wimg + 9728, tid);          // Wm2, overlaps epilogue
    store_act(As2, c, srow, false, rw0, cn0, g, t);    // H1 = silu_t -> bf16
    CP_WAIT0();
    __syncthreads();

    // ---- GEMM2: H1 @ Wm2 + bm2 -> msg ----
    warp_gemm(As2, BsT, sbias + 128, 8, rw0, cn0, g, t, c);
    __syncthreads();
    load_B_async(bsAddr, g_wimg + 2 * 9728, tid);      // Wc1, overlaps epilogue + aggregation
    store_act(As2, c, srow, true, rw0, cn0, g, t);     // msg = silu_f -> bf16 + f32 red
    CP_WAIT0();
    __syncthreads();

    // ---- GEMM3: msg @ Wc1 + bc1 -> x-weights ----
    warp_gemm(As2, BsT, sbias + 256, 8, rw0, cn0, g, t, c);
    __syncthreads();
    load_B_async(bsAddr, g_wimg + 3 * 9728, tid);      // Wv1, overlaps reduce + scatter
    reduce_rows(c, sbias + 512, (w >> 2) ? sredq : sredp, rw0, cn0, g, t);
    __syncthreads();
    if (tid < 128) {
        float tot = sredp[tid] + sredq[tid] + bc2[0];
        float wv = __fdividef(tot, ssq[tid] + 1e-8f);
        int rw = srow[tid];
        atomicAdd(outx + (size_t)rw * 3 + 0, srel[tid * 3 + 0] * wv);
        atomicAdd(outx + (size_t)rw * 3 + 1, srel[tid * 3 + 1] * wv);
        atomicAdd(outx + (size_t)rw * 3 + 2, srel[tid * 3 + 2] * wv);
    }
    CP_WAIT0();
    __syncthreads();

    // ---- GEMM4: msg @ Wv1 + bv1 -> v-weights ----
    warp_gemm(As2, BsT, sbias + 384, 8, rw0, cn0, g, t, c);
    reduce_rows(c, sbias + 640, (w >> 2) ? sredq : sredp, rw0, cn0, g, t);
    __syncthreads();
    if (tid < 128) {
        float tot = sredp[tid] + sredq[tid] + bv2[0];
        float wv = __fdividef(tot, ssq[tid] + 1e-8f);
        int rw = srow[tid];
        atomicAdd(outv + (size_t)rw * 3 + 0, srel[tid * 3 + 0] * wv);
        atomicAdd(outv + (size_t)rw * 3 + 1, srel[tid * 3 + 1] * wv);
        atomicAdd(outv + (size_t)rw * 3 + 2, srel[tid * 3 + 2] * wv);
    }
}

// ---------------- node kernel (FFMA2, proven) ----------------
__device__ __forceinline__ void gemm128n(const float* __restrict__ As_,
                                         const float* __restrict__ Bs_,
                                         const float* __restrict__ bias,
                                         int K, int ty, int tx,
                                         unsigned long long acc[8][4]) {
    const int c0 = tx * 2;
#pragma unroll
    for (int i = 0; i < 4; i++) {
        unsigned long long bi = pk2(bias[i * 32 + c0], bias[i * 32 + c0 + 1]);
#pragma unroll
        for (int j = 0; j < 8; j++) acc[j][i] = bi;
    }
    const float* ap = As_ + ty * 8;
    const float* bp = Bs_ + c0;
#pragma unroll 2
    for (int k = 0; k < K; k++) {
        float2 aA = *(const float2*)(ap + k * LDA + 0);
        float2 aB = *(const float2*)(ap + k * LDA + 2);
        float2 aC = *(const float2*)(ap + k * LDA + 4);
        float2 aD = *(const float2*)(ap + k * LDA + 6);
        unsigned long long a2[8];
        a2[0] = pk2(aA.x, aA.x); a2[1] = pk2(aA.y, aA.y);
        a2[2] = pk2(aB.x, aB.x); a2[3] = pk2(aB.y, aB.y);
        a2[4] = pk2(aC.x, aC.x); a2[5] = pk2(aC.y, aC.y);
        a2[6] = pk2(aD.x, aD.x); a2[7] = pk2(aD.y, aD.y);
        unsigned long long b0 = *(const unsigned long long*)(bp + k * 128 + 0);
        unsigned long long b1 = *(const unsigned long long*)(bp + k * 128 + 32);
        unsigned long long b2 = *(const unsigned long long*)(bp + k * 128 + 64);
        unsigned long long b3 = *(const unsigned long long*)(bp + k * 128 + 96);
#pragma unroll
        for (int j = 0; j < 8; j++) {
            f2fma(acc[j][0], a2[j], b0);
            f2fma(acc[j][1], a2[j], b1);
            f2fma(acc[j][2], a2[j], b2);
            f2fma(acc[j][3], a2[j], b3);
        }
    }
}

#define NODE_SMEM_FLOATS (24960 + 24576)
#define NODE_SMEM_BYTES  (NODE_SMEM_FLOATS * 4)

__global__ void __launch_bounds__(256, 1)
node_kernel(const float* __restrict__ h,
            const float* __restrict__ Wn1, const float* __restrict__ bn1,
            const float* __restrict__ Wn2, const float* __restrict__ bn2,
            float* __restrict__ out) {
    extern __shared__ float sm[];
    float* As = sm;
    float* Bs = As + 24960;
    const int tid = threadIdx.x;
    const int tx = tid & 15, ty = tid >> 4;
    const int n0 = blockIdx.x * 128;

    {
        int r = tid >> 1, part = tid & 1;
        int n = n0 + r;
        int nc = (n < NN) ? n : (NN - 1);
        const float4* hr = (const float4*)h + (size_t)nc * 16 + part * 8;
#pragma unroll
        for (int q = 0; q < 8; q++) {
            float4 f = hr[q];
            int k0 = part * 32 + q * 4;
            As[(k0 + 0) * LDA + r] = f.x; As[(k0 + 1) * LDA + r] = f.y;
            As[(k0 + 2) * LDA + r] = f.z; As[(k0 + 3) * LDA + r] = f.w;
        }
        const float4* ar = (const float4*)g_aggr + (size_t)nc * 32 + part * 16;
#pragma unroll
        for (int q = 0; q < 16; q++) {
            float4 f = ar[q];
            int k0 = 64 + part * 64 + q * 4;
            As[(k0 + 0) * LDA + r] = f.x; As[(k0 + 1) * LDA + r] = f.y;
            As[(k0 + 2) * LDA + r] = f.z; As[(k0 + 3) * LDA + r] = f.w;
        }
    }
    for (int i4 = tid; i4 < (192 * 128) / 4; i4 += 256)
        ((float4*)Bs)[i4] = ((const float4*)Wn1)[i4];
    __syncthreads();

    unsigned long long acc[8][4];
    gemm128n(As, Bs, bn1, 192, ty, tx, acc);
    __syncthreads();
#pragma unroll
    for (int j = 0; j < 8; j++) {
        int r = ty * 8 + j;
#pragma unroll
        for (int i = 0; i < 4; i++) {
            float2 tt = up2(acc[j][i]);
            int cc = i * 32 + tx * 2;
            As[(cc + 0) * LDA + r] = silu_f(tt.x);
            As[(cc + 1) * LDA + r] = silu_f(tt.y);
        }
    }
    for (int i4 = tid; i4 < (128 * 64) / 4; i4 += 256)
        ((float4*)Bs)[i4] = ((const float4*)Wn2)[i4];
    __syncthreads();

    unsigned long long a2b[8][2];
    {
        const int c0 = tx * 2;
#pragma unroll
        for (int i = 0; i < 2; i++) {
            unsigned long long bi = pk2(bn2[i * 32 + c0], bn2[i * 32 + c0 + 1]);
#pragma unroll
            for (int j = 0; j < 8; j++) a2b[j][i] = bi;
        }
        const float* ap = As + ty * 8;
        const float* bp = Bs + c0;
#pragma unroll 2
        for (int k = 0; k < 128; k++) {
            float2 aA = *(const float2*)(ap + k * LDA + 0);
            float2 aB = *(const float2*)(ap + k * LDA + 2);
            float2 aC = *(const float2*)(ap + k * LDA + 4);
            float2 aD = *(const float2*)(ap + k * LDA + 6);
            unsigned long long a2[8];
            a2[0] = pk2(aA.x, aA.x); a2[1] = pk2(aA.y, aA.y);
            a2[2] = pk2(aB.x, aB.x); a2[3] = pk2(aB.y, aB.y);
            a2[4] = pk2(aC.x, aC.x); a2[5] = pk2(aC.y, aC.y);
            a2[6] = pk2(aD.x, aD.x); a2[7] = pk2(aD.y, aD.y);
            unsigned long long b0 = *(const unsigned long long*)(bp + k * 64 + 0);
            unsigned long long b1 = *(const unsigned long long*)(bp + k * 64 + 32);
#pragma unroll
            for (int j = 0; j < 8; j++) {
                f2fma(a2b[j][0], a2[j], b0);
                f2fma(a2b[j][1], a2[j], b1);
            }
        }
    }
#pragma unroll
    for (int j = 0; j < 8; j++) {
        int n = n0 + ty * 8 + j;
        if (n < NN) {
#pragma unroll
            for (int i = 0; i < 2; i++) {
                int cc = i * 32 + tx * 2;
                float2 hv = *(const float2*)(h + (size_t)n * 64 + cc);
                float2 tt = up2(a2b[j][i]);
                float2 o; o.x = hv.x + tt.x; o.y = hv.y + tt.y;
                *(float2*)(out + (size_t)n * 64 + cc) = o;
            }
        }
    }
}

// ---------------- launch ----------------
extern "C" void kernel_launch(void* const* d_in, const int* in_sizes, int n_in,
                              void* d_out, int out_size) {
    const float* h   = (const float*)d_in[0];
    const float* x   = (const float*)d_in[1];
    const float* v   = (const float*)d_in[2];
    const int*   ei  = (const int*)d_in[3];
    const float* ea  = (const float*)d_in[4];
    const float* Wm1 = (const float*)d_in[5];
    const float* bm1 = (const float*)d_in[6];
    const float* Wm2 = (const float*)d_in[7];
    const float* bm2 = (const float*)d_in[8];
    const float* Wn1 = (const float*)d_in[9];
    const float* bn1 = (const float*)d_in[10];
    const float* Wn2 = (const float*)d_in[11];
    const float* bn2 = (const float*)d_in[12];
    const float* Wc1 = (const float*)d_in[13];
    const float* bc1 = (const float*)d_in[14];
    const float* Wc2 = (const float*)d_in[15];
    const float* bc2 = (const float*)d_in[16];
    const float* Wv1 = (const float*)d_in[17];
    const float* bv1 = (const float*)d_in[18];
    const float* Wv2 = (const float*)d_in[19];
    const float* bv2 = (const float*)d_in[20];
    float* out = (float*)d_out;

    cudaFuncSetAttribute(edge_mma_kernel, cudaFuncAttributeMaxDynamicSharedMemorySize, EDGE_SMEM_BYTES);
    cudaFuncSetAttribute(node_kernel, cudaFuncAttributeMaxDynamicSharedMemorySize, NODE_SMEM_BYTES);

    prep_kernel<<<(4 * 9728 + 255) / 256, 256>>>(Wm1, Wm2, Wc1, Wv1);
    init_kernel<<<2048, 256>>>(x, v, out);
    edge_mma_kernel<<<EE / 128, 256, EDGE_SMEM_BYTES>>>(
        h, x, ei, ea, bm1, bm2, bc1, bc2, bv1, bv2, Wc2, Wv2,
        out + (size_t)NN * 64, out + (size_t)NN * 64 + (size_t)NN * 3);
    node_kernel<<<(NN + 127) / 128, 256, NODE_SMEM_BYTES>>>(h, Wn1, bn1, Wn2, bn2, out);
}

// round 14
// speedup vs baseline: 5.0322x; 1.2461x over previous
#include <cuda_runtime.h>
#include <cstdint>

#define NN 100000
#define EE 1600000
#define LKA2 76    // As row stride (u32 pairs): 76 mod 32 = 12 -> 2-wavefront v2 frags
#define LKB2 76    // BsT row stride (u32 pairs), same property
#define NLKA 212   // node As stride (u32/tf32): 212 mod 32 = 20 -> conflict-free scalar frags
#define NLKB 136   // node Bs stride: 136 mod 32 = 8 -> conflict-free B frags

// ---------------- global scratch ----------------
__device__ float    g_aggr[(size_t)NN * 128];
__device__ uint32_t g_wimg[4 * 9728];   // bf16x2 images: Wm1|Wm2|Wc1|Wv1, layout [col][slot] = smem BsT

// ---------------- helpers ----------------
__device__ __forceinline__ float silu_t(float v) {          // 1-MUFU tanh silu (R13: delta vs exact = 1e-9)
    float t; asm("tanh.approx.f32 %0, %1;" : "=f"(t) : "f"(v * 0.5f));
    return fmaf(v * 0.5f, t, v * 0.5f);
}
// pack 2 floats -> bf16x2 (lo = first arg). PTX: first src -> HIGH half.
__device__ __forceinline__ uint32_t pkbf2(float lo, float hi) {
    uint32_t r; asm("cvt.rn.bf16x2.f32 %0, %1, %2;" : "=r"(r) : "f"(hi), "f"(lo)); return r;
}
__device__ __forceinline__ uint32_t rna_tf32(float f) {
    uint32_t u; asm("cvt.rna.tf32.f32 %0, %1;" : "=r"(u) : "f"(f)); return u;
}
__device__ __forceinline__ void mma16(float c[4], const uint32_t a[4], uint32_t b0, uint32_t b1) {
    asm volatile("mma.sync.aligned.m16n8k16.row.col.f32.bf16.bf16.f32 "
                 "{%0,%1,%2,%3}, {%4,%5,%6,%7}, {%8,%9}, {%0,%1,%2,%3};"
                 : "+f"(c[0]), "+f"(c[1]), "+f"(c[2]), "+f"(c[3])
                 : "r"(a[0]), "r"(a[1]), "r"(a[2]), "r"(a[3]), "r"(b0), "r"(b1));
}
__device__ __forceinline__ void mma8(float c[4], const uint32_t a[4], uint32_t b0, uint32_t b1) {
    asm volatile("mma.sync.aligned.m16n8k8.row.col.f32.tf32.tf32.f32 "
                 "{%0,%1,%2,%3}, {%4,%5,%6,%7}, {%8,%9}, {%0,%1,%2,%3};"
                 : "+f"(c[0]), "+f"(c[1]), "+f"(c[2]), "+f"(c[3])
                 : "r"(a[0]), "r"(a[1]), "r"(a[2]), "r"(a[3]), "r"(b0), "r"(b1));
}
__device__ __forceinline__ uint32_t smem_u32(const void* p) {
    uint32_t a;
    asm("{ .reg .u64 t; cvta.to.shared.u64 t, %1; cvt.u32.u64 %0, t; }" : "=r"(a) : "l"(p));
    return a;
}
__device__ __forceinline__ void cp16(uint32_t saddr, const void* g) {
    asm volatile("cp.async.cg.shared.global [%0], [%1], 16;" :: "r"(saddr), "l"(g) : "memory");
}
#define CP_COMMIT() asm volatile("cp.async.commit_group;" ::: "memory")
#define CP_WAIT0()  asm volatile("cp.async.wait_group 0;" ::: "memory")

// k-pair interleave: logical pair p -> physical slot. Valid only for p < 72 (full groups of 8).
__device__ __forceinline__ int physp(int p) {
    return (p & ~7) | ((p & 3) << 1) | ((p >> 2) & 1);
}

// ---------------- prep: bf16x2 interleaved-transposed weight images ----------------
__global__ void prep_kernel(const float* __restrict__ Wm1, const float* __restrict__ Wm2,
                            const float* __restrict__ Wc1, const float* __restrict__ Wv1) {
    int idx = blockIdx.x * blockDim.x + threadIdx.x;
    if (idx >= 4 * 9728) return;
    int img = idx / 9728;
    int r = idx - img * 9728;
    int n = r / 76;           // output col 0..127
    int kr = r - n * 76;      // logical k-pair 0..75
    if (kr >= 72) return;     // tail group would alias next column (R11 bug fix)
    const float* W = (img == 0) ? Wm1 : (img == 1) ? Wm2 : (img == 2) ? Wc1 : Wv1;
    int realK = (img == 0) ? 138 : 128;
    float lo = (2 * kr < realK) ? W[(2 * kr) * 128 + n] : 0.f;
    float hi = (2 * kr + 1 < realK) ? W[(2 * kr + 1) * 128 + n] : 0.f;
    g_wimg[img * 9728 + n * 76 + physp(kr)] = pkbf2(lo, hi);
}

// ---------------- init ----------------
__global__ void init_kernel(const float* __restrict__ x, const float* __restrict__ v,
                            float* __restrict__ out) {
    int idx = blockIdx.x * blockDim.x + threadIdx.x;
    int stride = gridDim.x * blockDim.x;
    for (int k = idx; k < NN * 128; k += stride) g_aggr[k] = 0.f;
    for (int k = idx; k < NN * 3; k += stride) {
        out[(size_t)NN * 64 + k] = x[k];
        out[(size_t)NN * 64 + (size_t)NN * 3 + k] = v[k];
    }
}

// ---------------- edge kernel pieces ----------------

__device__ __forceinline__ void load_B_async(uint32_t bsAddr, const uint32_t* __restrict__ gsrc, int tid) {
    for (int i = tid; i < 2432; i += 256)
        cp16(bsAddr + (uint32_t)i * 16u, (const char*)gsrc + (size_t)i * 16);
    CP_COMMIT();
}

__device__ __forceinline__ void warp_gemm(const uint32_t* __restrict__ As2,
                                          const uint32_t* __restrict__ BsT,
                                          const float* __restrict__ bias,
                                          int KB, int rw0, int cn0, int g, int t,
                                          float c[2][8][4]) {
#pragma unroll
    for (int nt = 0; nt < 8; nt++) {
        float b0v = bias[cn0 + nt * 8 + 2 * t];
        float b1v = bias[cn0 + nt * 8 + 2 * t + 1];
        c[0][nt][0] = b0v; c[0][nt][1] = b1v; c[0][nt][2] = b0v; c[0][nt][3] = b1v;
        c[1][nt][0] = b0v; c[1][nt][1] = b1v; c[1][nt][2] = b0v; c[1][nt][3] = b1v;
    }
    const uint32_t* arow = As2 + (rw0 + g) * LKA2 + 2 * t;
    const uint32_t* brow = BsT + (cn0 + g) * LKB2 + 2 * t;
#pragma unroll 1
    for (int kb = 0; kb < KB; kb++) {
        uint2 a00 = *(const uint2*)(arow + kb * 8);
        uint2 a01 = *(const uint2*)(arow + 8 * LKA2 + kb * 8);
        uint2 a10 = *(const uint2*)(arow + 16 * LKA2 + kb * 8);
        uint2 a11 = *(const uint2*)(arow + 24 * LKA2 + kb * 8);
        uint32_t a0[4] = {a00.x, a01.x, a00.y, a01.y};
        uint32_t a1[4] = {a10.x, a11.x, a10.y, a11.y};
#pragma unroll
        for (int nt = 0; nt < 8; nt++) {
            uint2 b = *(const uint2*)(brow + (nt * 8) * LKB2 + kb * 8);
            mma16(c[0][nt], a0, b.x, b.y);
            mma16(c[1][nt], a1, b.x, b.y);
        }
    }
}

// silu_t(c) -> As2 bf16 pairs; do_red: also f32 aggregation reds
__device__ __forceinline__ void store_act(uint32_t* __restrict__ As2, float c[2][8][4],
                                          const int* __restrict__ srow, bool do_red,
                                          int rw0, int cn0, int g, int t) {
#pragma unroll
    for (int mh = 0; mh < 2; mh++) {
        int r0 = rw0 + mh * 16 + g;
#pragma unroll
        for (int nt = 0; nt < 8; nt++) {
            int slot = (cn0 >> 1) + ((nt >> 1) << 3) + (t << 1) + (nt & 1);
            float v0 = silu_t(c[mh][nt][0]);
            float v1 = silu_t(c[mh][nt][1]);
            float v2 = silu_t(c[mh][nt][2]);
            float v3 = silu_t(c[mh][nt][3]);
            As2[r0 * LKA2 + slot] = pkbf2(v0, v1);
            As2[(r0 + 8) * LKA2 + slot] = pkbf2(v2, v3);
            if (do_red) {
                int col = cn0 + nt * 8 + 2 * t;
                float* d0 = g_aggr + (size_t)srow[r0] * 128 + col;
                float* d1 = g_aggr + (size_t)srow[r0 + 8] * 128 + col;
                asm volatile("red.global.add.v2.f32 [%0], {%1,%2};" :: "l"(d0), "f"(v0), "f"(v1) : "memory");
                asm volatile("red.global.add.v2.f32 [%0], {%1,%2};" :: "l"(d1), "f"(v2), "f"(v3) : "memory");
            }
        }
    }
}

// row-dot with w2 after silu_t, quad-reduce, stage per-row sums
__device__ __forceinline__ void reduce_rows(float c[2][8][4], const float* __restrict__ w2,
                                            float* __restrict__ sredh,
                                            int rw0, int cn0, int g, int t) {
#pragma unroll
    for (int mh = 0; mh < 2; mh++) {
        float s0 = 0.f, s1 = 0.f;
#pragma unroll
        for (int nt = 0; nt < 8; nt++) {
            int col = cn0 + nt * 8 + 2 * t;
            float w0 = w2[col], w1 = w2[col + 1];
            s0 += silu_t(c[mh][nt][0]) * w0 + silu_t(c[mh][nt][1]) * w1;
            s1 += silu_t(c[mh][nt][2]) * w0 + silu_t(c[mh][nt][3]) * w1;
        }
        s0 += __shfl_xor_sync(0xffffffffu, s0, 1);
        s0 += __shfl_xor_sync(0xffffffffu, s0, 2);
        s1 += __shfl_xor_sync(0xffffffffu, s1, 1);
        s1 += __shfl_xor_sync(0xffffffffu, s1, 2);
        if (t == 0) {
            sredh[rw0 + mh * 16 + g] = s0;
            sredh[rw0 + mh * 16 + g + 8] = s1;
        }
    }
}

// SMEM (u32): As2 9728 | BsT 9728 | sbias 768 | ssq 128 | srel 384 | sredp 128 | sredq 128 | srow 128 | scol 128
#define EDGE_SMEM_U32  (9728 + 9728 + 768 + 128 + 384 + 128 + 128 + 128 + 128)
#define EDGE_SMEM_BYTES (EDGE_SMEM_U32 * 4)   // 84992 -> 2 CTAs/SM

__global__ void __launch_bounds__(256, 2)
edge_mma_kernel(const float* __restrict__ h, const float* __restrict__ x,
                const int* __restrict__ ei, const float* __restrict__ ea,
                const float* __restrict__ bm1, const float* __restrict__ bm2,
                const float* __restrict__ bc1, const float* __restrict__ bc2,
                const float* __restrict__ bv1, const float* __restrict__ bv2,
                const float* __restrict__ Wc2, const float* __restrict__ Wv2,
                float* __restrict__ outx, float* __restrict__ outv) {
    extern __shared__ uint32_t smu[];
    uint32_t* As2  = smu;
    uint32_t* BsT  = As2 + 9728;
    float* sbias   = (float*)(BsT + 9728);
    float* ssq     = sbias + 768;
    float* srel    = ssq + 128;
    float* sredp   = srel + 384;
    float* sredq   = sredp + 128;
    int*   srow    = (int*)(sredq + 128);
    int*   scol    = srow + 128;

    const int tid = threadIdx.x;
    const int w = tid >> 5, lane = tid & 31;
    const int g = lane >> 2, t = lane & 3;
    const int rw0 = (w & 3) * 32, cn0 = (w >> 2) * 64;
    const int e0 = blockIdx.x * 128;
    const uint32_t bsAddr = smem_u32(BsT);

    load_B_async(bsAddr, g_wimg + 0, tid);

    if (tid < 128) {
        int e = e0 + tid;
        int r = ei[e], cc = ei[EE + e];
        srow[tid] = r; scol[tid] = cc;
        float dx = x[r * 3 + 0] - x[cc * 3 + 0];
        float dy = x[r * 3 + 1] - x[cc * 3 + 1];
        float dz = x[r * 3 + 2] - x[cc * 3 + 2];
        float sq = dx * dx + dy * dy + dz * dz;
        ssq[tid] = sq;
        srel[tid * 3 + 0] = dx; srel[tid * 3 + 1] = dy; srel[tid * 3 + 2] = dz;
        float4 ea0 = ((const float4*)(ea + (size_t)e * 8))[0];
        float4 ea1 = ((const float4*)(ea + (size_t)e * 8))[1];
        uint32_t* dst = As2 + tid * LKA2 + 64;
        dst[0] = pkbf2(sq, dz);
        dst[2] = pkbf2(ea0.x, ea0.y);
        dst[4] = pkbf2(ea0.z, ea0.w);
        dst[6] = pkbf2(ea1.x, ea1.y);
        dst[1] = pkbf2(ea1.z, ea1.w);
        dst[3] = 0u; dst[5] = 0u; dst[7] = 0u;
    } else {
        for (int i = tid - 128; i < 768; i += 128) {
            int j = i & 127, gg = i >> 7;
            sbias[i] = (gg == 0) ? bm1[j] : (gg == 1) ? bm2[j] : (gg == 2) ? bc1[j] :
                       (gg == 3) ? bv1[j] : (gg == 4) ? Wc2[j] : Wv2[j];
        }
    }
    __syncthreads();

    {
        int r = tid >> 1, part = tid & 1;
        int node = part ? scol[r] : srow[r];
        const float4* hp = (const float4*)(h + (size_t)node * 64);
        uint32_t* dst = As2 + r * LKA2;
        int pb = part * 32;
#pragma unroll
        for (int q = 0; q < 16; q++) {
            float4 f = hp[q];
            dst[physp(pb + q * 2)]     = pkbf2(f.x, f.y);
            dst[physp(pb + q * 2 + 1)] = pkbf2(f.z, f.w);
        }
    }
    CP_WAIT0();
    __syncthreads();

    float c[2][8][4];

    // GEMM1
    warp_gemm(As2, BsT, sbias + 0, 9, rw0, cn0, g, t, c);
    __syncthreads();
    load_B_async(bsAddr, g_wimg + 9728, tid);
    store_act(As2, c, srow, false, rw0, cn0, g, t);
    CP_WAIT0();
    __syncthreads();

    // GEMM2 -> msg + aggregation
    warp_gemm(As2, BsT, sbias + 128, 8, rw0, cn0, g, t, c);
    __syncthreads();
    load_B_async(bsAddr, g_wimg + 2 * 9728, tid);
    store_act(As2, c, srow, true, rw0, cn0, g, t);
    CP_WAIT0();
    __syncthreads();

    // GEMM3 -> x-weights
    warp_gemm(As2, BsT, sbias + 256, 8, rw0, cn0, g, t, c);
    __syncthreads();
    load_B_async(bsAddr, g_wimg + 3 * 9728, tid);
    reduce_rows(c, sbias + 512, (w >> 2) ? sredq : sredp, rw0, cn0, g, t);
    __syncthreads();
    if (tid < 128) {
        float tot = sredp[tid] + sredq[tid] + bc2[0];
        float wv = __fdividef(tot, ssq[tid] + 1e-8f);
        int rw = srow[tid];
        atomicAdd(outx + (size_t)rw * 3 + 0, srel[tid * 3 + 0] * wv);
        atomicAdd(outx + (size_t)rw * 3 + 1, srel[tid * 3 + 1] * wv);
        atomicAdd(outx + (size_t)rw * 3 + 2, srel[tid * 3 + 2] * wv);
    }
    CP_WAIT0();
    __syncthreads();

    // GEMM4 -> v-weights
    warp_gemm(As2, BsT, sbias + 384, 8, rw0, cn0, g, t, c);
    reduce_rows(c, sbias + 640, (w >> 2) ? sredq : sredp, rw0, cn0, g, t);
    __syncthreads();
    if (tid < 128) {
        float tot = sredp[tid] + sredq[tid] + bv2[0];
        float wv = __fdividef(tot, ssq[tid] + 1e-8f);
        int rw = srow[tid];
        atomicAdd(outv + (size_t)rw * 3 + 0, srel[tid * 3 + 0] * wv);
        atomicAdd(outv + (size_t)rw * 3 + 1, srel[tid * 3 + 1] * wv);
        atomicAdd(outv + (size_t)rw * 3 + 2, srel[tid * 3 + 2] * wv);
    }
}

// ---------------- node kernel: tf32 mma (round-8 validated machinery) ----------------
// SMEM (u32): As 128*212 = 27136 | Bs 192*136 = 26112
#define NODE_SMEM_U32  (27136 + 26112)
#define NODE_SMEM_BYTES (NODE_SMEM_U32 * 4)   // 212992

__global__ void __launch_bounds__(256, 1)
node_mma_kernel(const float* __restrict__ h,
                const float* __restrict__ Wn1, const float* __restrict__ bn1,
                const float* __restrict__ Wn2, const float* __restrict__ bn2,
                float* __restrict__ out) {
    extern __shared__ uint32_t smu[];
    uint32_t* As32 = smu;            // [128][NLKA] tf32
    uint32_t* Bs32 = As32 + 27136;   // [K][NLKB] tf32

    const int tid = threadIdx.x;
    const int w = tid >> 5, lane = tid & 31;
    const int g = lane >> 2, t = lane & 3;
    const int rw0 = (w & 3) * 32, cn0 = (w >> 2) * 64;
    const int n0 = blockIdx.x * 128;

    // ---- gather node_in = [h(64) | aggr(128)] as tf32 ----
    {
        int r = tid >> 1, part = tid & 1;
        int n = n0 + r;
        int nc = (n < NN) ? n : (NN - 1);
        uint32_t* dst = As32 + r * NLKA;
        if (part == 0) {
            const float4* hp = (const float4*)(h + (size_t)nc * 64);
#pragma unroll
            for (int q = 0; q < 16; q++) {
                float4 f = hp[q];
                dst[q * 4 + 0] = rna_tf32(f.x); dst[q * 4 + 1] = rna_tf32(f.y);
                dst[q * 4 + 2] = rna_tf32(f.z); dst[q * 4 + 3] = rna_tf32(f.w);
            }
            const float4* ap = (const float4*)(g_aggr + (size_t)nc * 128);
#pragma unroll
            for (int q = 0; q < 8; q++) {
                float4 f = ap[q];
                dst[64 + q * 4 + 0] = rna_tf32(f.x); dst[64 + q * 4 + 1] = rna_tf32(f.y);
                dst[64 + q * 4 + 2] = rna_tf32(f.z); dst[64 + q * 4 + 3] = rna_tf32(f.w);
            }
        } else {
            const float4* ap = (const float4*)(g_aggr + (size_t)nc * 128 + 32);
#pragma unroll
            for (int q = 0; q < 24; q++) {
                float4 f = ap[q];
                dst[96 + q * 4 + 0] = rna_tf32(f.x); dst[96 + q * 4 + 1] = rna_tf32(f.y);
                dst[96 + q * 4 + 2] = rna_tf32(f.z); dst[96 + q * 4 + 3] = rna_tf32(f.w);
            }
        }
    }
    // Bs <- Wn1 [192][128] tf32
    for (int idx = tid; idx < 192 * 32; idx += 256) {
        int k = idx >> 5, j = idx & 31;
        float4 f = ((const float4*)Wn1)[k * 32 + j];
        uint32_t* d = Bs32 + k * NLKB + j * 4;
        d[0] = rna_tf32(f.x); d[1] = rna_tf32(f.y); d[2] = rna_tf32(f.z); d[3] = rna_tf32(f.w);
    }
    __syncthreads();

    // ---- GEMM n1: node_in @ Wn1 + bn1, K=192 (24 k-blocks) ----
    float c[2][8][4];
#pragma unroll
    for (int nt = 0; nt < 8; nt++) {
        float b0v = bn1[cn0 + nt * 8 + 2 * t];
        float b1v = bn1[cn0 + nt * 8 + 2 * t + 1];
        c[0][nt][0] = b0v; c[0][nt][1] = b1v; c[0][nt][2] = b0v; c[0][nt][3] = b1v;
        c[1][nt][0] = b0v; c[1][nt][1] = b1v; c[1][nt][2] = b0v; c[1][nt][3] = b1v;
    }
    {
        const uint32_t* ar0 = As32 + (rw0 + g) * NLKA + t;
        const uint32_t* ar1 = As32 + (rw0 + 16 + g) * NLKA + t;
        const uint32_t* br  = Bs32 + t * NLKB + cn0 + g;
#pragma unroll 1
        for (int kb = 0; kb < 24; kb++) {
            uint32_t a0[4], a1[4];
            a0[0] = ar0[kb * 8];             a0[1] = ar0[8 * NLKA + kb * 8];
            a0[2] = ar0[kb * 8 + 4];         a0[3] = ar0[8 * NLKA + kb * 8 + 4];
            a1[0] = ar1[kb * 8];             a1[1] = ar1[8 * NLKA + kb * 8];
            a1[2] = ar1[kb * 8 + 4];         a1[3] = ar1[8 * NLKA + kb * 8 + 4];
#pragma unroll
            for (int nt = 0; nt < 8; nt++) {
                uint32_t b0 = br[(kb * 8) * NLKB + nt * 8];
                uint32_t b1 = br[(kb * 8 + 4) * NLKB + nt * 8];
                mma8(c[0][nt], a0, b0, b1);
                mma8(c[1][nt], a1, b0, b1);
            }
        }
    }
    __syncthreads();
    // epilogue: As <- tf32(silu(c)); Bs <- Wn2 [128][64]
#pragma unroll
    for (int mh = 0; mh < 2; mh++) {
        int r0 = rw0 + mh * 16 + g;
#pragma unroll
        for (int nt = 0; nt < 8; nt++) {
            int col = cn0 + nt * 8 + 2 * t;
            As32[r0 * NLKA + col]           = rna_tf32(silu_t(c[mh][nt][0]));
            As32[r0 * NLKA + col + 1]       = rna_tf32(silu_t(c[mh][nt][1]));
            As32[(r0 + 8) * NLKA + col]     = rna_tf32(silu_t(c[mh][nt][2]));
            As32[(r0 + 8) * NLKA + col + 1] = rna_tf32(silu_t(c[mh][nt][3]));
        }
    }
    for (int idx = tid; idx < 128 * 16; idx += 256) {
        int k = idx >> 4, j = idx & 15;
        float4 f = ((const float4*)Wn2)[k * 16 + j];
        uint32_t* d = Bs32 + k * NLKB + j * 4;
        d[0] = rna_tf32(f.x); d[1] = rna_tf32(f.y); d[2] = rna_tf32(f.z); d[3] = rna_tf32(f.w);
    }
    __syncthreads();

    // ---- GEMM n2: H1 @ Wn2 + bn2, K=128, N=64; warp w owns rows [w*16, w*16+16) ----
    {
        const int rz = w * 16;
        float c2[8][4];
#pragma unroll
        for (int nt = 0; nt < 8; nt++) {
            float b0v = bn2[nt * 8 + 2 * t];
            float b1v = bn2[nt * 8 + 2 * t + 1];
            c2[nt][0] = b0v; c2[nt][1] = b1v; c2[nt][2] = b0v; c2[nt][3] = b1v;
        }
        const uint32_t* ar = As32 + (rz + g) * NLKA + t;
        const uint32_t* br = Bs32 + t * NLKB + g;
#pragma unroll 1
        for (int kb = 0; kb < 16; kb++) {
            uint32_t a0[4];
            a0[0] = ar[kb * 8];       a0[1] = ar[8 * NLKA + kb * 8];
            a0[2] = ar[kb * 8 + 4];   a0[3] = ar[8 * NLKA + kb * 8 + 4];
#pragma unroll
            for (int nt = 0; nt < 8; nt++) {
                uint32_t b0 = br[(kb * 8) * NLKB + nt * 8];
                uint32_t b1 = br[(kb * 8 + 4) * NLKB + nt * 8];
                mma8(c2[nt], a0, b0, b1);
            }
        }
        // residual + store h_new
        int nA = n0 + rz + g, nB = nA + 8;
#pragma unroll
        for (int nt = 0; nt < 8; nt++) {
            int col = nt * 8 + 2 * t;
            if (nA < NN) {
                float2 hv = *(const float2*)(h + (size_t)nA * 64 + col);
                float2 o; o.x = hv.x + c2[nt][0]; o.y = hv.y + c2[nt][1];
                *(float2*)(out + (size_t)nA * 64 + col) = o;
            }
            if (nB < NN) {
                float2 hv = *(const float2*)(h + (size_t)nB * 64 + col);
                float2 o; o.x = hv.x + c2[nt][2]; o.y = hv.y + c2[nt][3];
                *(float2*)(out + (size_t)nB * 64 + col) = o;
            }
        }
    }
}

// ---------------- launch ----------------
extern "C" void kernel_launch(void* const* d_in, const int* in_sizes, int n_in,
                              void* d_out, int out_size) {
    const float* h   = (const float*)d_in[0];
    const float* x   = (const float*)d_in[1];
    const float* v   = (const float*)d_in[2];
    const int*   ei  = (const int*)d_in[3];
    const float* ea  = (const float*)d_in[4];
    const float* Wm1 = (const float*)d_in[5];
    const float* bm1 = (const float*)d_in[6];
    const float* Wm2 = (const float*)d_in[7];
    const float* bm2 = (const float*)d_in[8];
    const float* Wn1 = (const float*)d_in[9];
    const float* bn1 = (const float*)d_in[10];
    const float* Wn2 = (const float*)d_in[11];
    const float* bn2 = (const float*)d_in[12];
    const float* Wc1 = (const float*)d_in[13];
    const float* bc1 = (const float*)d_in[14];
    const float* Wc2 = (const float*)d_in[15];
    const float* bc2 = (const float*)d_in[16];
    const float* Wv1 = (const float*)d_in[17];
    const float* bv1 = (const float*)d_in[18];
    const float* Wv2 = (const float*)d_in[19];
    const float* bv2 = (const float*)d_in[20];
    float* out = (float*)d_out;

    cudaFuncSetAttribute(edge_mma_kernel, cudaFuncAttributeMaxDynamicSharedMemorySize, EDGE_SMEM_BYTES);
    cudaFuncSetAttribute(node_mma_kernel, cudaFuncAttributeMaxDynamicSharedMemorySize, NODE_SMEM_BYTES);

    prep_kernel<<<(4 * 9728 + 255) / 256, 256>>>(Wm1, Wm2, Wc1, Wv1);
    init_kernel<<<2048, 256>>>(x, v, out);
    edge_mma_kernel<<<EE / 128, 256, EDGE_SMEM_BYTES>>>(
        h, x, ei, ea, bm1, bm2, bc1, bc2, bv1, bv2, Wc2, Wv2,
        out + (size_t)NN * 64, out + (size_t)NN * 64 + (size_t)NN * 3);
    node_mma_kernel<<<(NN + 127) / 128, 256, NODE_SMEM_BYTES>>>(h, Wn1, bn1, Wn2, bn2, out);
}